// round 7
// baseline (speedup 1.0000x reference)
#include <cuda_runtime.h>
#include <cuda_bf16.h>
#include <cstdint>

// Problem constants (fixed by the reference)
#define NN      10000
#define KNN     32
#define DG      256
#define ODIM    256
#define XSTRIDE 512   // 2*DG

// Scratch
__device__ float g_h[NN * XSTRIDE];
__device__ __nv_bfloat16 g_Whi[2 * ODIM * DG];
__device__ __nv_bfloat16 g_Wlo[2 * ODIM * DG];

__device__ __forceinline__ uint32_t smem_u32(const void* p) {
    uint32_t a;
    asm("{ .reg .u64 t; cvta.to.shared.u64 t, %1; cvt.u32.u64 %0, t; }"
        : "=r"(a) : "l"(p));
    return a;
}

// split a float pair into packed bf16 hi / lo pairs
__device__ __forceinline__ void cvt_pair(float f0, float f1,
                                         uint32_t& hi, uint32_t& lo) {
    __nv_bfloat162 hp = __floats2bfloat162_rn(f0, f1);
    float2 hf = __bfloat1622float2(hp);
    __nv_bfloat162 lp = __floats2bfloat162_rn(f0 - hf.x, f1 - hf.y);
    hi = *(uint32_t*)&hp;
    lo = *(uint32_t*)&lp;
}

__device__ __forceinline__ void ldm_x4(uint32_t* r, uint32_t addr) {
    asm volatile("ldmatrix.sync.aligned.m8n8.x4.shared.b16 {%0,%1,%2,%3}, [%4];"
                 : "=r"(r[0]), "=r"(r[1]), "=r"(r[2]), "=r"(r[3]) : "r"(addr));
}

__device__ __forceinline__ void mma_bf16(float* d, const uint32_t* a,
                                         const uint32_t* b) {
    asm volatile(
        "mma.sync.aligned.m16n8k16.row.col.f32.bf16.bf16.f32 "
        "{%0,%1,%2,%3}, {%4,%5,%6,%7}, {%8,%9}, {%0,%1,%2,%3};"
        : "+f"(d[0]), "+f"(d[1]), "+f"(d[2]), "+f"(d[3])
        : "r"(a[0]), "r"(a[1]), "r"(a[2]), "r"(a[3]), "r"(b[0]), "r"(b[1]));
}

// ---------------------------------------------------------------------------
// Kernel 0: pre-split W1/W2 into bf16 hi/lo (done once, reused by 79 m-blocks)
// Grid (64, 2), 256 threads; each thread converts one float4.
// ---------------------------------------------------------------------------
__global__ __launch_bounds__(256)
void wcvt_kernel(const float* __restrict__ W1, const float* __restrict__ W2) {
    const int g = blockIdx.y;
    const float* __restrict__ W = g ? W2 : W1;
    int lin = (blockIdx.x * 256 + threadIdx.x) * 4;   // element index
    float4 v = *(const float4*)&W[lin];
    uint32_t h0, l0, h1, l1;
    cvt_pair(v.x, v.y, h0, l0);
    cvt_pair(v.z, v.w, h1, l1);
    *(uint2*)&g_Whi[g * ODIM * DG + lin] = make_uint2(h0, h1);
    *(uint2*)&g_Wlo[g * ODIM * DG + lin] = make_uint2(l0, l1);
}

// ---------------------------------------------------------------------------
// GEMM via HMMA (bf16 2-way split, 3 products, fp32 accumulate):
// Block: 128x128 tile, 8 warps (4m x 2n), warp tile 32x64.
// Grid (79, 2, 2) = (m-tiles, n-tiles, group). B loads pre-split bf16.
// ---------------------------------------------------------------------------
#define STR 40   // bf16 per smem row (32 k + 8 pad): 80B stride, conflict-free

__global__ __launch_bounds__(256)
void gemm_mma_kernel(const float* __restrict__ x,
                     const float* __restrict__ a1, const float* __restrict__ a2) {
    __shared__ __align__(16) __nv_bfloat16 sA[2][128 * STR];
    __shared__ __align__(16) __nv_bfloat16 sB[2][128 * STR];
    __shared__ float sFW[256];
    __shared__ float red[256];

    const int t    = threadIdx.x;
    const int lane = t & 31;
    const int wid  = t >> 5;
    const int wm   = wid >> 1;
    const int wn   = wid & 1;
    const int g    = blockIdx.z;
    const int i0   = blockIdx.x * 128;
    const int o0   = blockIdx.y * 128;
    const float* __restrict__ a = g ? a2 : a1;
    const __nv_bfloat16* __restrict__ Whi = g_Whi + g * ODIM * DG;
    const __nv_bfloat16* __restrict__ Wlo = g_Wlo + g * ODIM * DG;

    // ---- fused fw = softmax(a) ----
    float av = a[t];
    red[t] = av; __syncthreads();
    #pragma unroll
    for (int s = 128; s > 0; s >>= 1) {
        if (t < s) red[t] = fmaxf(red[t], red[t + s]);
        __syncthreads();
    }
    float amax = red[0]; __syncthreads();
    float e = expf(av - amax);
    red[t] = e; __syncthreads();
    #pragma unroll
    for (int s = 128; s > 0; s >>= 1) {
        if (t < s) red[t] += red[t + s];
        __syncthreads();
    }
    float esum = red[0]; __syncthreads();
    sFW[t] = e / esum;

    const uint32_t sA0 = smem_u32(&sA[0][0]);
    const uint32_t sA1 = smem_u32(&sA[1][0]);
    const uint32_t sB0 = smem_u32(&sB[0][0]);
    const uint32_t sB1 = smem_u32(&sB[1][0]);
    const uint32_t aoff = (uint32_t)(((wm * 32 + (lane & 15)) * STR +
                                      ((lane >> 4) & 1) * 8) * 2);
    const uint32_t boff = (uint32_t)(((wn * 64 + (lane & 7) + ((lane >> 4) & 1) * 8) * STR +
                                      ((lane >> 3) & 1) * 8) * 2);

    float acc[2][8][4];
    #pragma unroll
    for (int mt = 0; mt < 2; ++mt)
        #pragma unroll
        for (int nt = 0; nt < 8; ++nt)
            #pragma unroll
            for (int q = 0; q < 4; ++q) acc[mt][nt][q] = 0.f;

    for (int c = 0; c < 8; ++c) {
        const int k0 = c * 32;
        #pragma unroll
        for (int q = 0; q < 4; ++q) {
            int lin = q * 256 + t;
            int row = lin >> 3;
            int k   = (lin & 7) * 4;
            // A (x rows): fp32 -> split
            float4 v = make_float4(0.f, 0.f, 0.f, 0.f);
            if (i0 + row < NN)
                v = *(const float4*)&x[(size_t)(i0 + row) * XSTRIDE + g * DG + k0 + k];
            uint32_t h0, l0, h1, l1;
            cvt_pair(v.x, v.y, h0, l0);
            cvt_pair(v.z, v.w, h1, l1);
            *(uint2*)&sA[0][row * STR + k] = make_uint2(h0, h1);
            *(uint2*)&sA[1][row * STR + k] = make_uint2(l0, l1);
            // B (W rows): pre-split bf16, straight copy
            size_t widx = (size_t)(o0 + row) * DG + k0 + k;
            *(uint2*)&sB[0][row * STR + k] = *(const uint2*)&Whi[widx];
            *(uint2*)&sB[1][row * STR + k] = *(const uint2*)&Wlo[widx];
        }
        __syncthreads();

        #pragma unroll
        for (int ks = 0; ks < 2; ++ks) {
            uint32_t ah[2][4], al[2][4];
            ldm_x4(ah[0], sA0 + aoff + ks * 32);
            ldm_x4(ah[1], sA0 + aoff + 16 * STR * 2 + ks * 32);
            ldm_x4(al[0], sA1 + aoff + ks * 32);
            ldm_x4(al[1], sA1 + aoff + 16 * STR * 2 + ks * 32);
            #pragma unroll
            for (int nt2 = 0; nt2 < 4; ++nt2) {
                uint32_t bh[4], bl[4];
                ldm_x4(bh, sB0 + boff + nt2 * 16 * STR * 2 + ks * 32);
                ldm_x4(bl, sB1 + boff + nt2 * 16 * STR * 2 + ks * 32);
                #pragma unroll
                for (int mt = 0; mt < 2; ++mt) {
                    mma_bf16(acc[mt][nt2 * 2],     ah[mt], bh);
                    mma_bf16(acc[mt][nt2 * 2],     ah[mt], bl);
                    mma_bf16(acc[mt][nt2 * 2],     al[mt], bh);
                    mma_bf16(acc[mt][nt2 * 2 + 1], ah[mt], bh + 2);
                    mma_bf16(acc[mt][nt2 * 2 + 1], ah[mt], bl + 2);
                    mma_bf16(acc[mt][nt2 * 2 + 1], al[mt], bh + 2);
                }
            }
        }
        __syncthreads();
    }

    // ---- epilogue: scale by fw, clip, store ----
    #pragma unroll
    for (int mt = 0; mt < 2; ++mt) {
        int ra = i0 + wm * 32 + mt * 16 + (lane >> 2);
        int rb = ra + 8;
        #pragma unroll
        for (int nt = 0; nt < 8; ++nt) {
            int colg = o0 + wn * 64 + nt * 8 + (lane & 3) * 2;
            float f0 = sFW[colg], f1 = sFW[colg + 1];
            if (ra < NN) {
                float2 v;
                v.x = fminf(1.f, fmaxf(-1.f, acc[mt][nt][0] * f0));
                v.y = fminf(1.f, fmaxf(-1.f, acc[mt][nt][1] * f1));
                *(float2*)&g_h[(size_t)ra * XSTRIDE + g * DG + colg] = v;
            }
            if (rb < NN) {
                float2 v;
                v.x = fminf(1.f, fmaxf(-1.f, acc[mt][nt][2] * f0));
                v.y = fminf(1.f, fmaxf(-1.f, acc[mt][nt][3] * f1));
                *(float2*)&g_h[(size_t)rb * XSTRIDE + g * DG + colg] = v;
            }
        }
    }
}

// ---------------------------------------------------------------------------
// Attention v3: one block per (node, group), 256 threads, 8 warps.
// Warp w owns neighbors 4w..4w+3; lane owns 8 contiguous columns.
// Halves SHFL count vs v2; gathers remain fully coalesced (2x512B per row).
// ---------------------------------------------------------------------------
__global__ __launch_bounds__(256)
void attn_kernel(const int* __restrict__ graph, float* __restrict__ out) {
    const int i = blockIdx.x;
    const int g = blockIdx.y;

    __shared__ int   idxs[KNN];
    __shared__ float ovs[DG];
    __shared__ float att[KNN];
    __shared__ float agg[8][260];   // 260-pad: 16B-aligned rows, conflict-free

    const int t    = threadIdx.x;
    const int lane = t & 31;
    const int w    = t >> 5;

    if (t < KNN) idxs[t] = __ldg(&graph[(size_t)i * KNN + t]);
    if (t < 64)
        *(float4*)&ovs[t * 4] =
            __ldcg((const float4*)&g_h[(size_t)i * XSTRIDE + g * DG + t * 4]);
    __syncthreads();

    // gather: 4 neighbor rows per warp, lane covers cols [lane*8, lane*8+8)
    const float* __restrict__ base = g_h + g * DG + lane * 8;
    float4 nb[4][2];
    #pragma unroll
    for (int jj = 0; jj < 4; ++jj) {
        const float* rp = base + (size_t)idxs[w * 4 + jj] * XSTRIDE;
        nb[jj][0] = __ldcg((const float4*)rp);
        nb[jj][1] = __ldcg((const float4*)(rp + 4));
    }
    float4 ov0 = *(const float4*)&ovs[lane * 8];
    float4 ov1 = *(const float4*)&ovs[lane * 8 + 4];

    // scores
    #pragma unroll
    for (int jj = 0; jj < 4; ++jj) {
        float dx0 = ov0.x - nb[jj][0].x, dy0 = ov0.y - nb[jj][0].y;
        float dz0 = ov0.z - nb[jj][0].z, dw0 = ov0.w - nb[jj][0].w;
        float dx1 = ov1.x - nb[jj][1].x, dy1 = ov1.y - nb[jj][1].y;
        float dz1 = ov1.z - nb[jj][1].z, dw1 = ov1.w - nb[jj][1].w;
        float s = ((dx0 * dx0 + dy0 * dy0) + (dz0 * dz0 + dw0 * dw0)) +
                  ((dx1 * dx1 + dy1 * dy1) + (dz1 * dz1 + dw1 * dw1));
        #pragma unroll
        for (int off = 16; off; off >>= 1) s += __shfl_xor_sync(0xffffffffu, s, off);
        if (lane == 0) att[w * 4 + jj] = -s;
    }
    __syncthreads();

    // softmax over 32 scores (warp 0)
    if (t < KNN) {
        float s = att[t];
        float m = s;
        #pragma unroll
        for (int off = 16; off; off >>= 1) m = fmaxf(m, __shfl_xor_sync(0xffffffffu, m, off));
        float e = __expf(s - m);
        float sum = e;
        #pragma unroll
        for (int off = 16; off; off >>= 1) sum += __shfl_xor_sync(0xffffffffu, sum, off);
        att[t] = e / sum;
    }
    __syncthreads();

    // weighted partial aggregate (4 neighbors per warp) -> smem
    float4 a0 = make_float4(0.f, 0.f, 0.f, 0.f);
    float4 a1 = make_float4(0.f, 0.f, 0.f, 0.f);
    #pragma unroll
    for (int jj = 0; jj < 4; ++jj) {
        float wt = att[w * 4 + jj];
        a0.x = fmaf(wt, nb[jj][0].x, a0.x);
        a0.y = fmaf(wt, nb[jj][0].y, a0.y);
        a0.z = fmaf(wt, nb[jj][0].z, a0.z);
        a0.w = fmaf(wt, nb[jj][0].w, a0.w);
        a1.x = fmaf(wt, nb[jj][1].x, a1.x);
        a1.y = fmaf(wt, nb[jj][1].y, a1.y);
        a1.z = fmaf(wt, nb[jj][1].z, a1.z);
        a1.w = fmaf(wt, nb[jj][1].w, a1.w);
    }
    *(float4*)&agg[w][lane * 8]     = a0;
    *(float4*)&agg[w][lane * 8 + 4] = a1;
    __syncthreads();

    // cross-warp column sum + store (thread t = column t)
    float s = 0.f;
    #pragma unroll
    for (int w8 = 0; w8 < 8; ++w8) s += agg[w8][t];
    out[(size_t)i * XSTRIDE + g * DG + t] = s;
}

// ---------------------------------------------------------------------------
// Launch
// ---------------------------------------------------------------------------
extern "C" void kernel_launch(void* const* d_in, const int* in_sizes, int n_in,
                              void* d_out, int out_size) {
    const float* x     = (const float*)d_in[0];
    const float* W1    = (const float*)d_in[1];
    const float* a1    = (const float*)d_in[2];
    const float* W2    = (const float*)d_in[3];
    const float* a2    = (const float*)d_in[4];
    const int*   graph = (const int*)d_in[5];
    float* out = (float*)d_out;

    dim3 wgrid(ODIM * DG / (256 * 4), 2);
    wcvt_kernel<<<wgrid, 256>>>(W1, W2);

    dim3 ggrid((NN + 127) / 128, 2, 2);
    gemm_mma_kernel<<<ggrid, 256>>>(x, a1, a2);

    dim3 agrid(NN, 2);
    attn_kernel<<<agrid, 256>>>(graph, out);
}

// round 8
// speedup vs baseline: 1.1984x; 1.1984x over previous
#include <cuda_runtime.h>
#include <cuda_bf16.h>
#include <cstdint>

// Problem constants (fixed by the reference)
#define NN      10000
#define KNN     32
#define DG      256
#define ODIM    256
#define XSTRIDE 512   // 2*DG

// Scratch
__device__ float g_h[NN * XSTRIDE];
__device__ __nv_bfloat16 g_xhi[NN * XSTRIDE];
__device__ __nv_bfloat16 g_xlo[NN * XSTRIDE];
__device__ __nv_bfloat16 g_Whi[2 * ODIM * DG];
__device__ __nv_bfloat16 g_Wlo[2 * ODIM * DG];

__device__ __forceinline__ uint32_t smem_u32(const void* p) {
    uint32_t a;
    asm("{ .reg .u64 t; cvta.to.shared.u64 t, %1; cvt.u32.u64 %0, t; }"
        : "=r"(a) : "l"(p));
    return a;
}

// split a float pair into packed bf16 hi / lo pairs
__device__ __forceinline__ void cvt_pair(float f0, float f1,
                                         uint32_t& hi, uint32_t& lo) {
    __nv_bfloat162 hp = __floats2bfloat162_rn(f0, f1);
    float2 hf = __bfloat1622float2(hp);
    __nv_bfloat162 lp = __floats2bfloat162_rn(f0 - hf.x, f1 - hf.y);
    hi = *(uint32_t*)&hp;
    lo = *(uint32_t*)&lp;
}

__device__ __forceinline__ void ldm_x4(uint32_t* r, uint32_t addr) {
    asm volatile("ldmatrix.sync.aligned.m8n8.x4.shared.b16 {%0,%1,%2,%3}, [%4];"
                 : "=r"(r[0]), "=r"(r[1]), "=r"(r[2]), "=r"(r[3]) : "r"(addr));
}

__device__ __forceinline__ void mma_bf16(float* d, const uint32_t* a,
                                         const uint32_t* b) {
    asm volatile(
        "mma.sync.aligned.m16n8k16.row.col.f32.bf16.bf16.f32 "
        "{%0,%1,%2,%3}, {%4,%5,%6,%7}, {%8,%9}, {%0,%1,%2,%3};"
        : "+f"(d[0]), "+f"(d[1]), "+f"(d[2]), "+f"(d[3])
        : "r"(a[0]), "r"(a[1]), "r"(a[2]), "r"(a[3]), "r"(b[0]), "r"(b[1]));
}

// ---------------------------------------------------------------------------
// Kernel 0: pre-split x, W1, W2 into global bf16 hi/lo tables (grid-stride).
// ---------------------------------------------------------------------------
#define XF4  (NN * XSTRIDE / 4)          // 1,280,000 float4
#define WF4  (2 * ODIM * DG / 4)         // 32,768 float4
#define TOTF4 (XF4 + WF4)

__global__ __launch_bounds__(256)
void cvt_kernel(const float* __restrict__ x,
                const float* __restrict__ W1, const float* __restrict__ W2) {
    for (int idx = blockIdx.x * 256 + threadIdx.x; idx < TOTF4;
         idx += gridDim.x * 256) {
        uint32_t h0, l0, h1, l1;
        if (idx < XF4) {
            float4 v = *(const float4*)&x[(size_t)idx * 4];
            cvt_pair(v.x, v.y, h0, l0);
            cvt_pair(v.z, v.w, h1, l1);
            *(uint2*)&g_xhi[(size_t)idx * 4] = make_uint2(h0, h1);
            *(uint2*)&g_xlo[(size_t)idx * 4] = make_uint2(l0, l1);
        } else {
            int wlin = (idx - XF4) * 4;
            int g = wlin >= ODIM * DG;
            int off = wlin - g * ODIM * DG;
            const float* __restrict__ W = g ? W2 : W1;
            float4 v = *(const float4*)&W[off];
            cvt_pair(v.x, v.y, h0, l0);
            cvt_pair(v.z, v.w, h1, l1);
            *(uint2*)&g_Whi[wlin] = make_uint2(h0, h1);
            *(uint2*)&g_Wlo[wlin] = make_uint2(l0, l1);
        }
    }
}

// ---------------------------------------------------------------------------
// GEMM via HMMA (bf16 2-way split, 3 products, fp32 accumulate):
// Block: 128x128 tile, 8 warps (4m x 2n), warp tile 32x64.
// Grid (79, 2, 2). Fills are pure bf16 copies (no conversion in hot loop).
// ---------------------------------------------------------------------------
#define STR 40   // bf16 per smem row (32 k + 8 pad): 80B stride, conflict-free

__global__ __launch_bounds__(256)
void gemm_mma_kernel(const float* __restrict__ a1, const float* __restrict__ a2) {
    __shared__ __align__(16) __nv_bfloat16 sA[2][128 * STR];
    __shared__ __align__(16) __nv_bfloat16 sB[2][128 * STR];
    __shared__ float sFW[256];
    __shared__ float red[256];

    const int t    = threadIdx.x;
    const int lane = t & 31;
    const int wid  = t >> 5;
    const int wm   = wid >> 1;
    const int wn   = wid & 1;
    const int g    = blockIdx.z;
    const int i0   = blockIdx.x * 128;
    const int o0   = blockIdx.y * 128;
    const float* __restrict__ a = g ? a2 : a1;
    const __nv_bfloat16* __restrict__ Whi = g_Whi + g * ODIM * DG;
    const __nv_bfloat16* __restrict__ Wlo = g_Wlo + g * ODIM * DG;

    // ---- fused fw = softmax(a) ----
    float av = a[t];
    red[t] = av; __syncthreads();
    #pragma unroll
    for (int s = 128; s > 0; s >>= 1) {
        if (t < s) red[t] = fmaxf(red[t], red[t + s]);
        __syncthreads();
    }
    float amax = red[0]; __syncthreads();
    float e = expf(av - amax);
    red[t] = e; __syncthreads();
    #pragma unroll
    for (int s = 128; s > 0; s >>= 1) {
        if (t < s) red[t] += red[t + s];
        __syncthreads();
    }
    float esum = red[0]; __syncthreads();
    sFW[t] = e / esum;

    const uint32_t sA0 = smem_u32(&sA[0][0]);
    const uint32_t sA1 = smem_u32(&sA[1][0]);
    const uint32_t sB0 = smem_u32(&sB[0][0]);
    const uint32_t sB1 = smem_u32(&sB[1][0]);
    const uint32_t aoff = (uint32_t)(((wm * 32 + (lane & 15)) * STR +
                                      ((lane >> 4) & 1) * 8) * 2);
    const uint32_t boff = (uint32_t)(((wn * 64 + (lane & 7) + ((lane >> 4) & 1) * 8) * STR +
                                      ((lane >> 3) & 1) * 8) * 2);

    float acc[2][8][4];
    #pragma unroll
    for (int mt = 0; mt < 2; ++mt)
        #pragma unroll
        for (int nt = 0; nt < 8; ++nt)
            #pragma unroll
            for (int q = 0; q < 4; ++q) acc[mt][nt][q] = 0.f;

    for (int c = 0; c < 8; ++c) {
        const int k0 = c * 32;
        #pragma unroll
        for (int q = 0; q < 4; ++q) {
            int lin = q * 256 + t;
            int row = lin >> 3;
            int k   = (lin & 7) * 4;
            // A (x rows): pre-split bf16, straight copy
            uint2 ah2 = make_uint2(0u, 0u), al2 = make_uint2(0u, 0u);
            if (i0 + row < NN) {
                size_t xi = (size_t)(i0 + row) * XSTRIDE + g * DG + k0 + k;
                ah2 = *(const uint2*)&g_xhi[xi];
                al2 = *(const uint2*)&g_xlo[xi];
            }
            *(uint2*)&sA[0][row * STR + k] = ah2;
            *(uint2*)&sA[1][row * STR + k] = al2;
            // B (W rows): pre-split bf16, straight copy
            size_t widx = (size_t)(o0 + row) * DG + k0 + k;
            *(uint2*)&sB[0][row * STR + k] = *(const uint2*)&Whi[widx];
            *(uint2*)&sB[1][row * STR + k] = *(const uint2*)&Wlo[widx];
        }
        __syncthreads();

        #pragma unroll
        for (int ks = 0; ks < 2; ++ks) {
            uint32_t ah[2][4], al[2][4];
            ldm_x4(ah[0], sA0 + aoff + ks * 32);
            ldm_x4(ah[1], sA0 + aoff + 16 * STR * 2 + ks * 32);
            ldm_x4(al[0], sA1 + aoff + ks * 32);
            ldm_x4(al[1], sA1 + aoff + 16 * STR * 2 + ks * 32);
            #pragma unroll
            for (int nt2 = 0; nt2 < 4; ++nt2) {
                uint32_t bh[4], bl[4];
                ldm_x4(bh, sB0 + boff + nt2 * 16 * STR * 2 + ks * 32);
                ldm_x4(bl, sB1 + boff + nt2 * 16 * STR * 2 + ks * 32);
                #pragma unroll
                for (int mt = 0; mt < 2; ++mt) {
                    mma_bf16(acc[mt][nt2 * 2],     ah[mt], bh);
                    mma_bf16(acc[mt][nt2 * 2],     ah[mt], bl);
                    mma_bf16(acc[mt][nt2 * 2],     al[mt], bh);
                    mma_bf16(acc[mt][nt2 * 2 + 1], ah[mt], bh + 2);
                    mma_bf16(acc[mt][nt2 * 2 + 1], ah[mt], bl + 2);
                    mma_bf16(acc[mt][nt2 * 2 + 1], al[mt], bh + 2);
                }
            }
        }
        __syncthreads();
    }

    // ---- epilogue: scale by fw, clip, store ----
    #pragma unroll
    for (int mt = 0; mt < 2; ++mt) {
        int ra = i0 + wm * 32 + mt * 16 + (lane >> 2);
        int rb = ra + 8;
        #pragma unroll
        for (int nt = 0; nt < 8; ++nt) {
            int colg = o0 + wn * 64 + nt * 8 + (lane & 3) * 2;
            float f0 = sFW[colg], f1 = sFW[colg + 1];
            if (ra < NN) {
                float2 v;
                v.x = fminf(1.f, fmaxf(-1.f, acc[mt][nt][0] * f0));
                v.y = fminf(1.f, fmaxf(-1.f, acc[mt][nt][1] * f1));
                *(float2*)&g_h[(size_t)ra * XSTRIDE + g * DG + colg] = v;
            }
            if (rb < NN) {
                float2 v;
                v.x = fminf(1.f, fmaxf(-1.f, acc[mt][nt][2] * f0));
                v.y = fminf(1.f, fmaxf(-1.f, acc[mt][nt][3] * f1));
                *(float2*)&g_h[(size_t)rb * XSTRIDE + g * DG + colg] = v;
            }
        }
    }
}

// ---------------------------------------------------------------------------
// Attention (proven v2): one block per (node, group), 256 threads, neighbors
// in registers, q = t&63 (16B lane stride -> 4 wavefronts per warp-load).
// ---------------------------------------------------------------------------
__global__ __launch_bounds__(256)
void attn_kernel(const int* __restrict__ graph, float* __restrict__ out) {
    const int i = blockIdx.x;
    const int g = blockIdx.y;

    __shared__ int   idxs[KNN];
    __shared__ float part[2 * KNN];
    __shared__ float score[KNN];
    __shared__ float4 agg[4][64];

    const int t = threadIdx.x;
    if (t < KNN) idxs[t] = __ldg(&graph[(size_t)i * KNN + t]);
    __syncthreads();

    const int q    = t & 63;
    const int jb   = t >> 6;
    const int w    = t >> 5;
    const int lane = t & 31;

    const float* __restrict__ base = g_h + g * DG + q * 4;
    float4 ov = __ldcg((const float4*)(base + (size_t)i * XSTRIDE));

    float4 nbv[8];
    #pragma unroll
    for (int r = 0; r < 8; ++r)
        nbv[r] = __ldcg((const float4*)(base + (size_t)idxs[4 * r + jb] * XSTRIDE));

    #pragma unroll
    for (int r = 0; r < 8; ++r) {
        float dx = ov.x - nbv[r].x, dy = ov.y - nbv[r].y;
        float dz = ov.z - nbv[r].z, dw = ov.w - nbv[r].w;
        float s = dx * dx + dy * dy + dz * dz + dw * dw;
        #pragma unroll
        for (int off = 16; off; off >>= 1) s += __shfl_xor_sync(0xffffffffu, s, off);
        if (lane == 0) part[(4 * r + jb) * 2 + (w & 1)] = s;
    }
    __syncthreads();

    if (t < KNN) {
        float s = -(part[2 * t] + part[2 * t + 1]);
        float m = s;
        #pragma unroll
        for (int off = 16; off; off >>= 1) m = fmaxf(m, __shfl_xor_sync(0xffffffffu, m, off));
        float e = __expf(s - m);
        float sum = e;
        #pragma unroll
        for (int off = 16; off; off >>= 1) sum += __shfl_xor_sync(0xffffffffu, sum, off);
        score[t] = e / sum;
    }
    __syncthreads();

    float4 acc = make_float4(0.f, 0.f, 0.f, 0.f);
    #pragma unroll
    for (int r = 0; r < 8; ++r) {
        float wt = score[4 * r + jb];
        acc.x = fmaf(wt, nbv[r].x, acc.x);
        acc.y = fmaf(wt, nbv[r].y, acc.y);
        acc.z = fmaf(wt, nbv[r].z, acc.z);
        acc.w = fmaf(wt, nbv[r].w, acc.w);
    }
    agg[jb][q] = acc;
    __syncthreads();

    if (t < 64) {
        float4 s0 = agg[0][t], s1 = agg[1][t], s2 = agg[2][t], s3 = agg[3][t];
        float4 o;
        o.x = (s0.x + s1.x) + (s2.x + s3.x);
        o.y = (s0.y + s1.y) + (s2.y + s3.y);
        o.z = (s0.z + s1.z) + (s2.z + s3.z);
        o.w = (s0.w + s1.w) + (s2.w + s3.w);
        *(float4*)&out[(size_t)i * XSTRIDE + g * DG + t * 4] = o;
    }
}

// ---------------------------------------------------------------------------
// Launch
// ---------------------------------------------------------------------------
extern "C" void kernel_launch(void* const* d_in, const int* in_sizes, int n_in,
                              void* d_out, int out_size) {
    const float* x     = (const float*)d_in[0];
    const float* W1    = (const float*)d_in[1];
    const float* a1    = (const float*)d_in[2];
    const float* W2    = (const float*)d_in[3];
    const float* a2    = (const float*)d_in[4];
    const int*   graph = (const int*)d_in[5];
    float* out = (float*)d_out;

    cvt_kernel<<<2560, 256>>>(x, W1, W2);

    dim3 ggrid((NN + 127) / 128, 2, 2);
    gemm_mma_kernel<<<ggrid, 256>>>(a1, a2);

    dim3 agrid(NN, 2);
    attn_kernel<<<agrid, 256>>>(graph, out);
}

// round 9
// speedup vs baseline: 1.2366x; 1.0319x over previous
#include <cuda_runtime.h>
#include <cuda_bf16.h>
#include <cstdint>

// Problem constants (fixed by the reference)
#define NN      10000
#define KNN     32
#define DG      256
#define ODIM    256
#define XSTRIDE 512   // 2*DG

// Scratch
__device__ float g_h[NN * XSTRIDE];
__device__ __nv_bfloat16 g_Whi[2 * ODIM * DG];
__device__ __nv_bfloat16 g_Wlo[2 * ODIM * DG];

__device__ __forceinline__ uint32_t smem_u32(const void* p) {
    uint32_t a;
    asm("{ .reg .u64 t; cvta.to.shared.u64 t, %1; cvt.u32.u64 %0, t; }"
        : "=r"(a) : "l"(p));
    return a;
}

// split a float pair into packed bf16 hi / lo pairs
__device__ __forceinline__ void cvt_pair(float f0, float f1,
                                         uint32_t& hi, uint32_t& lo) {
    __nv_bfloat162 hp = __floats2bfloat162_rn(f0, f1);
    float2 hf = __bfloat1622float2(hp);
    __nv_bfloat162 lp = __floats2bfloat162_rn(f0 - hf.x, f1 - hf.y);
    hi = *(uint32_t*)&hp;
    lo = *(uint32_t*)&lp;
}

__device__ __forceinline__ void ldm_x4(uint32_t* r, uint32_t addr) {
    asm volatile("ldmatrix.sync.aligned.m8n8.x4.shared.b16 {%0,%1,%2,%3}, [%4];"
                 : "=r"(r[0]), "=r"(r[1]), "=r"(r[2]), "=r"(r[3]) : "r"(addr));
}

__device__ __forceinline__ void mma_bf16(float* d, const uint32_t* a,
                                         const uint32_t* b) {
    asm volatile(
        "mma.sync.aligned.m16n8k16.row.col.f32.bf16.bf16.f32 "
        "{%0,%1,%2,%3}, {%4,%5,%6,%7}, {%8,%9}, {%0,%1,%2,%3};"
        : "+f"(d[0]), "+f"(d[1]), "+f"(d[2]), "+f"(d[3])
        : "r"(a[0]), "r"(a[1]), "r"(a[2]), "r"(a[3]), "r"(b[0]), "r"(b[1]));
}

// ---------------------------------------------------------------------------
// Kernel 0: pre-split W1/W2 into bf16 hi/lo (W reused by all 157 m-blocks).
// ---------------------------------------------------------------------------
__global__ __launch_bounds__(256)
void wcvt_kernel(const float* __restrict__ W1, const float* __restrict__ W2) {
    int idx = blockIdx.x * 256 + threadIdx.x;          // float4 index
    int wlin = idx * 4;
    int g = wlin >= ODIM * DG;
    int off = wlin - g * ODIM * DG;
    const float* __restrict__ W = g ? W2 : W1;
    float4 v = *(const float4*)&W[off];
    uint32_t h0, l0, h1, l1;
    cvt_pair(v.x, v.y, h0, l0);
    cvt_pair(v.z, v.w, h1, l1);
    *(uint2*)&g_Whi[wlin] = make_uint2(h0, h1);
    *(uint2*)&g_Wlo[wlin] = make_uint2(l0, l1);
}

// ---------------------------------------------------------------------------
// GEMM via HMMA (bf16 2-way split, 3 products, fp32 accumulate):
// Block tile 64x256 (BN = full output width -> x converted exactly once).
// 8 warps (2m x 4n), warp tile 32x64. Grid (157, 2) = (m-tiles, group).
// Dynamic smem: A 64xSTR hi/lo + B 256xSTR hi/lo (52KB).
// ---------------------------------------------------------------------------
#define STR 40   // bf16 per smem row (32 k + 8 pad): 80B stride, conflict-free

#define DSM_A_HI  0
#define DSM_A_LO  (64 * STR * 2)                 // 5120
#define DSM_B_HI  (2 * 64 * STR * 2)             // 10240
#define DSM_B_LO  (DSM_B_HI + 256 * STR * 2)     // 30720
#define DSM_FW    (DSM_B_LO + 256 * STR * 2)     // 51200
#define DSM_RED   (DSM_FW + 1024)                // 52224
#define DSM_TOTAL (DSM_RED + 1024)               // 53248

__global__ __launch_bounds__(256)
void gemm_mma_kernel(const float* __restrict__ x,
                     const float* __restrict__ a1, const float* __restrict__ a2) {
    extern __shared__ char dsm[];
    __nv_bfloat16* sAhi = (__nv_bfloat16*)(dsm + DSM_A_HI);
    __nv_bfloat16* sAlo = (__nv_bfloat16*)(dsm + DSM_A_LO);
    __nv_bfloat16* sBhi = (__nv_bfloat16*)(dsm + DSM_B_HI);
    __nv_bfloat16* sBlo = (__nv_bfloat16*)(dsm + DSM_B_LO);
    float* sFW = (float*)(dsm + DSM_FW);
    float* red = (float*)(dsm + DSM_RED);

    const int t    = threadIdx.x;
    const int lane = t & 31;
    const int wid  = t >> 5;
    const int wm   = wid >> 2;     // 0..1
    const int wn   = wid & 3;      // 0..3
    const int g    = blockIdx.y;
    const int i0   = blockIdx.x * 64;
    const float* __restrict__ a = g ? a2 : a1;
    const __nv_bfloat16* __restrict__ Whi = g_Whi + g * ODIM * DG;
    const __nv_bfloat16* __restrict__ Wlo = g_Wlo + g * ODIM * DG;

    // ---- fused fw = softmax(a) ----
    float av = a[t];
    red[t] = av; __syncthreads();
    #pragma unroll
    for (int s = 128; s > 0; s >>= 1) {
        if (t < s) red[t] = fmaxf(red[t], red[t + s]);
        __syncthreads();
    }
    float amax = red[0]; __syncthreads();
    float e = expf(av - amax);
    red[t] = e; __syncthreads();
    #pragma unroll
    for (int s = 128; s > 0; s >>= 1) {
        if (t < s) red[t] += red[t + s];
        __syncthreads();
    }
    float esum = red[0]; __syncthreads();
    sFW[t] = e / esum;

    const uint32_t sA0 = smem_u32(sAhi);
    const uint32_t sA1 = smem_u32(sAlo);
    const uint32_t sB0 = smem_u32(sBhi);
    const uint32_t sB1 = smem_u32(sBlo);
    const uint32_t aoff = (uint32_t)(((wm * 32 + (lane & 15)) * STR +
                                      ((lane >> 4) & 1) * 8) * 2);
    const uint32_t boff = (uint32_t)(((wn * 64 + (lane & 7) + ((lane >> 4) & 1) * 8) * STR +
                                      ((lane >> 3) & 1) * 8) * 2);

    float acc[2][8][4];
    #pragma unroll
    for (int mt = 0; mt < 2; ++mt)
        #pragma unroll
        for (int nt = 0; nt < 8; ++nt)
            #pragma unroll
            for (int q = 0; q < 4; ++q) acc[mt][nt][q] = 0.f;

    // A-fill coords: thread -> (row 0..63, kseg 0/8/16/24)
    const int arow = t >> 2;
    const int akk  = (t & 3) * 8;
    const bool arow_ok = (i0 + arow) < NN;
    const float* __restrict__ xrow =
        x + (size_t)(i0 + arow) * XSTRIDE + g * DG + akk;

    for (int c = 0; c < 8; ++c) {
        const int k0 = c * 32;
        // ---- A: load fp32 x (once per row/group), split, store ----
        {
            float4 v0 = make_float4(0.f, 0.f, 0.f, 0.f);
            float4 v1 = make_float4(0.f, 0.f, 0.f, 0.f);
            if (arow_ok) {
                v0 = *(const float4*)(xrow + k0);
                v1 = *(const float4*)(xrow + k0 + 4);
            }
            uint32_t h0, l0, h1, l1, h2, l2, h3, l3;
            cvt_pair(v0.x, v0.y, h0, l0);
            cvt_pair(v0.z, v0.w, h1, l1);
            cvt_pair(v1.x, v1.y, h2, l2);
            cvt_pair(v1.z, v1.w, h3, l3);
            *(uint4*)&sAhi[arow * STR + akk] = make_uint4(h0, h1, h2, h3);
            *(uint4*)&sAlo[arow * STR + akk] = make_uint4(l0, l1, l2, l3);
        }
        // ---- B: pre-split bf16 copy (4 segments of 8k per thread) ----
        #pragma unroll
        for (int q = 0; q < 4; ++q) {
            int lin = q * 256 + t;
            int row = lin >> 2;
            int kk  = (lin & 3) * 8;
            size_t widx = (size_t)row * DG + k0 + kk;
            *(uint4*)&sBhi[row * STR + kk] = *(const uint4*)&Whi[widx];
            *(uint4*)&sBlo[row * STR + kk] = *(const uint4*)&Wlo[widx];
        }
        __syncthreads();

        #pragma unroll
        for (int ks = 0; ks < 2; ++ks) {
            uint32_t ah[2][4], al[2][4];
            ldm_x4(ah[0], sA0 + aoff + ks * 32);
            ldm_x4(ah[1], sA0 + aoff + 16 * STR * 2 + ks * 32);
            ldm_x4(al[0], sA1 + aoff + ks * 32);
            ldm_x4(al[1], sA1 + aoff + 16 * STR * 2 + ks * 32);
            #pragma unroll
            for (int nt2 = 0; nt2 < 4; ++nt2) {
                uint32_t bh[4], bl[4];
                ldm_x4(bh, sB0 + boff + nt2 * 16 * STR * 2 + ks * 32);
                ldm_x4(bl, sB1 + boff + nt2 * 16 * STR * 2 + ks * 32);
                #pragma unroll
                for (int mt = 0; mt < 2; ++mt) {
                    mma_bf16(acc[mt][nt2 * 2],     ah[mt], bh);
                    mma_bf16(acc[mt][nt2 * 2],     ah[mt], bl);
                    mma_bf16(acc[mt][nt2 * 2],     al[mt], bh);
                    mma_bf16(acc[mt][nt2 * 2 + 1], ah[mt], bh + 2);
                    mma_bf16(acc[mt][nt2 * 2 + 1], ah[mt], bl + 2);
                    mma_bf16(acc[mt][nt2 * 2 + 1], al[mt], bh + 2);
                }
            }
        }
        __syncthreads();
    }

    // ---- epilogue: scale by fw, clip, store ----
    #pragma unroll
    for (int mt = 0; mt < 2; ++mt) {
        int ra = i0 + wm * 32 + mt * 16 + (lane >> 2);
        int rb = ra + 8;
        #pragma unroll
        for (int nt = 0; nt < 8; ++nt) {
            int colg = wn * 64 + nt * 8 + (lane & 3) * 2;   // 0..255
            float f0 = sFW[colg], f1 = sFW[colg + 1];
            if (ra < NN) {
                float2 v;
                v.x = fminf(1.f, fmaxf(-1.f, acc[mt][nt][0] * f0));
                v.y = fminf(1.f, fmaxf(-1.f, acc[mt][nt][1] * f1));
                *(float2*)&g_h[(size_t)ra * XSTRIDE + g * DG + colg] = v;
            }
            if (rb < NN) {
                float2 v;
                v.x = fminf(1.f, fmaxf(-1.f, acc[mt][nt][2] * f0));
                v.y = fminf(1.f, fmaxf(-1.f, acc[mt][nt][3] * f1));
                *(float2*)&g_h[(size_t)rb * XSTRIDE + g * DG + colg] = v;
            }
        }
    }
}

// ---------------------------------------------------------------------------
// Attention (proven v2, unchanged): one block per (node, group), 256 threads,
// neighbors in registers, q = t&63 (16B lane stride, coalesced 512B/warp).
// ---------------------------------------------------------------------------
__global__ __launch_bounds__(256)
void attn_kernel(const int* __restrict__ graph, float* __restrict__ out) {
    const int i = blockIdx.x;
    const int g = blockIdx.y;

    __shared__ int   idxs[KNN];
    __shared__ float part[2 * KNN];
    __shared__ float score[KNN];
    __shared__ float4 agg[4][64];

    const int t = threadIdx.x;
    if (t < KNN) idxs[t] = __ldg(&graph[(size_t)i * KNN + t]);
    __syncthreads();

    const int q    = t & 63;
    const int jb   = t >> 6;
    const int w    = t >> 5;
    const int lane = t & 31;

    const float* __restrict__ base = g_h + g * DG + q * 4;
    float4 ov = __ldcg((const float4*)(base + (size_t)i * XSTRIDE));

    float4 nbv[8];
    #pragma unroll
    for (int r = 0; r < 8; ++r)
        nbv[r] = __ldcg((const float4*)(base + (size_t)idxs[4 * r + jb] * XSTRIDE));

    #pragma unroll
    for (int r = 0; r < 8; ++r) {
        float dx = ov.x - nbv[r].x, dy = ov.y - nbv[r].y;
        float dz = ov.z - nbv[r].z, dw = ov.w - nbv[r].w;
        float s = dx * dx + dy * dy + dz * dz + dw * dw;
        #pragma unroll
        for (int off = 16; off; off >>= 1) s += __shfl_xor_sync(0xffffffffu, s, off);
        if (lane == 0) part[(4 * r + jb) * 2 + (w & 1)] = s;
    }
    __syncthreads();

    if (t < KNN) {
        float s = -(part[2 * t] + part[2 * t + 1]);
        float m = s;
        #pragma unroll
        for (int off = 16; off; off >>= 1) m = fmaxf(m, __shfl_xor_sync(0xffffffffu, m, off));
        float e = __expf(s - m);
        float sum = e;
        #pragma unroll
        for (int off = 16; off; off >>= 1) sum += __shfl_xor_sync(0xffffffffu, sum, off);
        score[t] = e / sum;
    }
    __syncthreads();

    float4 acc = make_float4(0.f, 0.f, 0.f, 0.f);
    #pragma unroll
    for (int r = 0; r < 8; ++r) {
        float wt = score[4 * r + jb];
        acc.x = fmaf(wt, nbv[r].x, acc.x);
        acc.y = fmaf(wt, nbv[r].y, acc.y);
        acc.z = fmaf(wt, nbv[r].z, acc.z);
        acc.w = fmaf(wt, nbv[r].w, acc.w);
    }
    agg[jb][q] = acc;
    __syncthreads();

    if (t < 64) {
        float4 s0 = agg[0][t], s1 = agg[1][t], s2 = agg[2][t], s3 = agg[3][t];
        float4 o;
        o.x = (s0.x + s1.x) + (s2.x + s3.x);
        o.y = (s0.y + s1.y) + (s2.y + s3.y);
        o.z = (s0.z + s1.z) + (s2.z + s3.z);
        o.w = (s0.w + s1.w) + (s2.w + s3.w);
        *(float4*)&out[(size_t)i * XSTRIDE + g * DG + t * 4] = o;
    }
}

// ---------------------------------------------------------------------------
// Launch
// ---------------------------------------------------------------------------
extern "C" void kernel_launch(void* const* d_in, const int* in_sizes, int n_in,
                              void* d_out, int out_size) {
    const float* x     = (const float*)d_in[0];
    const float* W1    = (const float*)d_in[1];
    const float* a1    = (const float*)d_in[2];
    const float* W2    = (const float*)d_in[3];
    const float* a2    = (const float*)d_in[4];
    const int*   graph = (const int*)d_in[5];
    float* out = (float*)d_out;

    static int smem_set = 0;
    if (!smem_set) {
        cudaFuncSetAttribute(gemm_mma_kernel,
                             cudaFuncAttributeMaxDynamicSharedMemorySize, DSM_TOTAL);
        smem_set = 1;
    }

    wcvt_kernel<<<2 * ODIM * DG / (256 * 4), 256>>>(W1, W2);

    dim3 ggrid((NN + 63) / 64, 2);
    gemm_mma_kernel<<<ggrid, 256, DSM_TOTAL>>>(x, a1, a2);

    dim3 agrid(NN, 2);
    attn_kernel<<<agrid, 256>>>(graph, out);
}

// round 10
// speedup vs baseline: 1.4120x; 1.1418x over previous
#include <cuda_runtime.h>
#include <cuda_bf16.h>
#include <cuda_fp16.h>
#include <cstdint>

// Problem constants (fixed by the reference)
#define NN      10000
#define KNN     32
#define DG      256
#define ODIM    256
#define XSTRIDE 512   // 2*DG

// Scratch: fp16 transformed feature table + pre-split W
__device__ __half g_hh[NN * XSTRIDE];
__device__ __nv_bfloat16 g_Whi[2 * ODIM * DG];
__device__ __nv_bfloat16 g_Wlo[2 * ODIM * DG];

__device__ __forceinline__ uint32_t smem_u32(const void* p) {
    uint32_t a;
    asm("{ .reg .u64 t; cvta.to.shared.u64 t, %1; cvt.u32.u64 %0, t; }"
        : "=r"(a) : "l"(p));
    return a;
}

// split a float pair into packed bf16 hi / lo pairs
__device__ __forceinline__ void cvt_pair(float f0, float f1,
                                         uint32_t& hi, uint32_t& lo) {
    __nv_bfloat162 hp = __floats2bfloat162_rn(f0, f1);
    float2 hf = __bfloat1622float2(hp);
    __nv_bfloat162 lp = __floats2bfloat162_rn(f0 - hf.x, f1 - hf.y);
    hi = *(uint32_t*)&hp;
    lo = *(uint32_t*)&lp;
}

__device__ __forceinline__ void ldm_x4(uint32_t* r, uint32_t addr) {
    asm volatile("ldmatrix.sync.aligned.m8n8.x4.shared.b16 {%0,%1,%2,%3}, [%4];"
                 : "=r"(r[0]), "=r"(r[1]), "=r"(r[2]), "=r"(r[3]) : "r"(addr));
}

__device__ __forceinline__ void mma_bf16(float* d, const uint32_t* a,
                                         const uint32_t* b) {
    asm volatile(
        "mma.sync.aligned.m16n8k16.row.col.f32.bf16.bf16.f32 "
        "{%0,%1,%2,%3}, {%4,%5,%6,%7}, {%8,%9}, {%0,%1,%2,%3};"
        : "+f"(d[0]), "+f"(d[1]), "+f"(d[2]), "+f"(d[3])
        : "r"(a[0]), "r"(a[1]), "r"(a[2]), "r"(a[3]), "r"(b[0]), "r"(b[1]));
}

// unpack 8 halves (uint4) into 8 floats
__device__ __forceinline__ void h8_to_f8(uint4 u, float* f) {
    float2 p;
    p = __half22float2(*(__half2*)&u.x); f[0] = p.x; f[1] = p.y;
    p = __half22float2(*(__half2*)&u.y); f[2] = p.x; f[3] = p.y;
    p = __half22float2(*(__half2*)&u.z); f[4] = p.x; f[5] = p.y;
    p = __half22float2(*(__half2*)&u.w); f[6] = p.x; f[7] = p.y;
}

// ---------------------------------------------------------------------------
// Kernel 0: pre-split W1/W2 into bf16 hi/lo.
// ---------------------------------------------------------------------------
__global__ __launch_bounds__(256)
void wcvt_kernel(const float* __restrict__ W1, const float* __restrict__ W2) {
    int idx = blockIdx.x * 256 + threadIdx.x;
    int wlin = idx * 4;
    int g = wlin >= ODIM * DG;
    int off = wlin - g * ODIM * DG;
    const float* __restrict__ W = g ? W2 : W1;
    float4 v = *(const float4*)&W[off];
    uint32_t h0, l0, h1, l1;
    cvt_pair(v.x, v.y, h0, l0);
    cvt_pair(v.z, v.w, h1, l1);
    *(uint2*)&g_Whi[wlin] = make_uint2(h0, h1);
    *(uint2*)&g_Wlo[wlin] = make_uint2(l0, l1);
}

// ---------------------------------------------------------------------------
// GEMM via HMMA (bf16 2-way split, 3 products, fp32 accumulate):
// Block tile 64x256, 8 warps (2m x 4n). Grid (157, 2). Epilogue -> fp16 table.
// ---------------------------------------------------------------------------
#define STR 40   // bf16 per smem row (32 k + 8 pad)

#define DSM_A_HI  0
#define DSM_A_LO  (64 * STR * 2)
#define DSM_B_HI  (2 * 64 * STR * 2)
#define DSM_B_LO  (DSM_B_HI + 256 * STR * 2)
#define DSM_FW    (DSM_B_LO + 256 * STR * 2)
#define DSM_RED   (DSM_FW + 1024)
#define DSM_TOTAL (DSM_RED + 1024)

__global__ __launch_bounds__(256)
void gemm_mma_kernel(const float* __restrict__ x,
                     const float* __restrict__ a1, const float* __restrict__ a2) {
    extern __shared__ char dsm[];
    __nv_bfloat16* sAhi = (__nv_bfloat16*)(dsm + DSM_A_HI);
    __nv_bfloat16* sAlo = (__nv_bfloat16*)(dsm + DSM_A_LO);
    __nv_bfloat16* sBhi = (__nv_bfloat16*)(dsm + DSM_B_HI);
    __nv_bfloat16* sBlo = (__nv_bfloat16*)(dsm + DSM_B_LO);
    float* sFW = (float*)(dsm + DSM_FW);
    float* red = (float*)(dsm + DSM_RED);

    const int t    = threadIdx.x;
    const int lane = t & 31;
    const int wid  = t >> 5;
    const int wm   = wid >> 2;
    const int wn   = wid & 3;
    const int g    = blockIdx.y;
    const int i0   = blockIdx.x * 64;
    const float* __restrict__ a = g ? a2 : a1;
    const __nv_bfloat16* __restrict__ Whi = g_Whi + g * ODIM * DG;
    const __nv_bfloat16* __restrict__ Wlo = g_Wlo + g * ODIM * DG;

    // ---- fused fw = softmax(a) ----
    float av = a[t];
    red[t] = av; __syncthreads();
    #pragma unroll
    for (int s = 128; s > 0; s >>= 1) {
        if (t < s) red[t] = fmaxf(red[t], red[t + s]);
        __syncthreads();
    }
    float amax = red[0]; __syncthreads();
    float e = expf(av - amax);
    red[t] = e; __syncthreads();
    #pragma unroll
    for (int s = 128; s > 0; s >>= 1) {
        if (t < s) red[t] += red[t + s];
        __syncthreads();
    }
    float esum = red[0]; __syncthreads();
    sFW[t] = e / esum;

    const uint32_t sA0 = smem_u32(sAhi);
    const uint32_t sA1 = smem_u32(sAlo);
    const uint32_t sB0 = smem_u32(sBhi);
    const uint32_t sB1 = smem_u32(sBlo);
    const uint32_t aoff = (uint32_t)(((wm * 32 + (lane & 15)) * STR +
                                      ((lane >> 4) & 1) * 8) * 2);
    const uint32_t boff = (uint32_t)(((wn * 64 + (lane & 7) + ((lane >> 4) & 1) * 8) * STR +
                                      ((lane >> 3) & 1) * 8) * 2);

    float acc[2][8][4];
    #pragma unroll
    for (int mt = 0; mt < 2; ++mt)
        #pragma unroll
        for (int nt = 0; nt < 8; ++nt)
            #pragma unroll
            for (int q = 0; q < 4; ++q) acc[mt][nt][q] = 0.f;

    const int arow = t >> 2;
    const int akk  = (t & 3) * 8;
    const bool arow_ok = (i0 + arow) < NN;
    const float* __restrict__ xrow =
        x + (size_t)(i0 + arow) * XSTRIDE + g * DG + akk;

    for (int c = 0; c < 8; ++c) {
        const int k0 = c * 32;
        {
            float4 v0 = make_float4(0.f, 0.f, 0.f, 0.f);
            float4 v1 = make_float4(0.f, 0.f, 0.f, 0.f);
            if (arow_ok) {
                v0 = *(const float4*)(xrow + k0);
                v1 = *(const float4*)(xrow + k0 + 4);
            }
            uint32_t h0, l0, h1, l1, h2, l2, h3, l3;
            cvt_pair(v0.x, v0.y, h0, l0);
            cvt_pair(v0.z, v0.w, h1, l1);
            cvt_pair(v1.x, v1.y, h2, l2);
            cvt_pair(v1.z, v1.w, h3, l3);
            *(uint4*)&sAhi[arow * STR + akk] = make_uint4(h0, h1, h2, h3);
            *(uint4*)&sAlo[arow * STR + akk] = make_uint4(l0, l1, l2, l3);
        }
        #pragma unroll
        for (int q = 0; q < 4; ++q) {
            int lin = q * 256 + t;
            int row = lin >> 2;
            int kk  = (lin & 3) * 8;
            size_t widx = (size_t)row * DG + k0 + kk;
            *(uint4*)&sBhi[row * STR + kk] = *(const uint4*)&Whi[widx];
            *(uint4*)&sBlo[row * STR + kk] = *(const uint4*)&Wlo[widx];
        }
        __syncthreads();

        #pragma unroll
        for (int ks = 0; ks < 2; ++ks) {
            uint32_t ah[2][4], al[2][4];
            ldm_x4(ah[0], sA0 + aoff + ks * 32);
            ldm_x4(ah[1], sA0 + aoff + 16 * STR * 2 + ks * 32);
            ldm_x4(al[0], sA1 + aoff + ks * 32);
            ldm_x4(al[1], sA1 + aoff + 16 * STR * 2 + ks * 32);
            #pragma unroll
            for (int nt2 = 0; nt2 < 4; ++nt2) {
                uint32_t bh[4], bl[4];
                ldm_x4(bh, sB0 + boff + nt2 * 16 * STR * 2 + ks * 32);
                ldm_x4(bl, sB1 + boff + nt2 * 16 * STR * 2 + ks * 32);
                #pragma unroll
                for (int mt = 0; mt < 2; ++mt) {
                    mma_bf16(acc[mt][nt2 * 2],     ah[mt], bh);
                    mma_bf16(acc[mt][nt2 * 2],     ah[mt], bl);
                    mma_bf16(acc[mt][nt2 * 2],     al[mt], bh);
                    mma_bf16(acc[mt][nt2 * 2 + 1], ah[mt], bh + 2);
                    mma_bf16(acc[mt][nt2 * 2 + 1], ah[mt], bl + 2);
                    mma_bf16(acc[mt][nt2 * 2 + 1], al[mt], bh + 2);
                }
            }
        }
        __syncthreads();
    }

    // ---- epilogue: scale by fw, clip, convert fp16, store ----
    #pragma unroll
    for (int mt = 0; mt < 2; ++mt) {
        int ra = i0 + wm * 32 + mt * 16 + (lane >> 2);
        int rb = ra + 8;
        #pragma unroll
        for (int nt = 0; nt < 8; ++nt) {
            int colg = wn * 64 + nt * 8 + (lane & 3) * 2;
            float f0 = sFW[colg], f1 = sFW[colg + 1];
            if (ra < NN) {
                float vx = fminf(1.f, fmaxf(-1.f, acc[mt][nt][0] * f0));
                float vy = fminf(1.f, fmaxf(-1.f, acc[mt][nt][1] * f1));
                *(__half2*)&g_hh[(size_t)ra * XSTRIDE + g * DG + colg] =
                    __floats2half2_rn(vx, vy);
            }
            if (rb < NN) {
                float vx = fminf(1.f, fmaxf(-1.f, acc[mt][nt][2] * f0));
                float vy = fminf(1.f, fmaxf(-1.f, acc[mt][nt][3] * f1));
                *(__half2*)&g_hh[(size_t)rb * XSTRIDE + g * DG + colg] =
                    __floats2half2_rn(vx, vy);
            }
        }
    }
}

// ---------------------------------------------------------------------------
// Attention v4 (fp16 table): one block per (node, group), 256 threads.
// Warp w owns neighbors {w, w+8, w+16, w+24}; one warp spans a FULL 512B row
// (lane covers 8 cols = 16B). Gather bytes halved vs fp32.
// ---------------------------------------------------------------------------
__global__ __launch_bounds__(256)
void attn_kernel(const int* __restrict__ graph, float* __restrict__ out) {
    const int i = blockIdx.x;
    const int g = blockIdx.y;

    __shared__ int   idxs[KNN];
    __shared__ float score[KNN];
    __shared__ float agg[8][DG];   // 8KB

    const int t    = threadIdx.x;
    const int lane = t & 31;
    const int w    = t >> 5;

    if (t < KNN) idxs[t] = __ldg(&graph[(size_t)i * KNN + t]);
    __syncthreads();

    const __half* __restrict__ base = g_hh + g * DG + lane * 8;

    // self row: all warps hit the same 4 lines (L1-cached after first)
    uint4 ovu = *(const uint4*)(base + (size_t)i * XSTRIDE);
    float ovf[8];
    h8_to_f8(ovu, ovf);

    // gather 4 neighbor rows per warp (512B contiguous each, MLP=4)
    uint4 nbu[4];
    #pragma unroll
    for (int r = 0; r < 4; ++r)
        nbu[r] = __ldcg((const uint4*)(base + (size_t)idxs[w + 8 * r] * XSTRIDE));
    float nbf[4][8];
    #pragma unroll
    for (int r = 0; r < 4; ++r) h8_to_f8(nbu[r], nbf[r]);

    // scores: full-row warp reduction per neighbor
    #pragma unroll
    for (int r = 0; r < 4; ++r) {
        float s = 0.f;
        #pragma unroll
        for (int d = 0; d < 8; ++d) {
            float diff = ovf[d] - nbf[r][d];
            s = fmaf(diff, diff, s);
        }
        #pragma unroll
        for (int off = 16; off; off >>= 1) s += __shfl_xor_sync(0xffffffffu, s, off);
        if (lane == 0) score[w + 8 * r] = -s;
    }
    __syncthreads();

    // softmax over 32 scores (warp 0)
    if (t < KNN) {
        float s = score[t];
        float m = s;
        #pragma unroll
        for (int off = 16; off; off >>= 1) m = fmaxf(m, __shfl_xor_sync(0xffffffffu, m, off));
        float e = __expf(s - m);
        float sum = e;
        #pragma unroll
        for (int off = 16; off; off >>= 1) sum += __shfl_xor_sync(0xffffffffu, sum, off);
        score[t] = e / sum;
    }
    __syncthreads();

    // weighted partial aggregate (4 neighbors per warp)
    float acc[8];
    #pragma unroll
    for (int d = 0; d < 8; ++d) acc[d] = 0.f;
    #pragma unroll
    for (int r = 0; r < 4; ++r) {
        float wt = score[w + 8 * r];
        #pragma unroll
        for (int d = 0; d < 8; ++d)
            acc[d] = fmaf(wt, nbf[r][d], acc[d]);
    }
    *(float4*)&agg[w][lane * 8]     = make_float4(acc[0], acc[1], acc[2], acc[3]);
    *(float4*)&agg[w][lane * 8 + 4] = make_float4(acc[4], acc[5], acc[6], acc[7]);
    __syncthreads();

    // cross-warp column sum + store (thread t = column t)
    float s = 0.f;
    #pragma unroll
    for (int w8 = 0; w8 < 8; ++w8) s += agg[w8][t];
    out[(size_t)i * XSTRIDE + g * DG + t] = s;
}

// ---------------------------------------------------------------------------
// Launch
// ---------------------------------------------------------------------------
extern "C" void kernel_launch(void* const* d_in, const int* in_sizes, int n_in,
                              void* d_out, int out_size) {
    const float* x     = (const float*)d_in[0];
    const float* W1    = (const float*)d_in[1];
    const float* a1    = (const float*)d_in[2];
    const float* W2    = (const float*)d_in[3];
    const float* a2    = (const float*)d_in[4];
    const int*   graph = (const int*)d_in[5];
    float* out = (float*)d_out;

    static int smem_set = 0;
    if (!smem_set) {
        cudaFuncSetAttribute(gemm_mma_kernel,
                             cudaFuncAttributeMaxDynamicSharedMemorySize, DSM_TOTAL);
        smem_set = 1;
    }

    wcvt_kernel<<<2 * ODIM * DG / (256 * 4), 256>>>(W1, W2);

    dim3 ggrid((NN + 63) / 64, 2);
    gemm_mma_kernel<<<ggrid, 256, DSM_TOTAL>>>(x, a1, a2);

    dim3 agrid(NN, 2);
    attn_kernel<<<agrid, 256>>>(graph, out);
}

// round 11
// speedup vs baseline: 1.4625x; 1.0358x over previous
#include <cuda_runtime.h>
#include <cuda_bf16.h>
#include <cuda_fp16.h>
#include <cstdint>

// Problem constants (fixed by the reference)
#define NN      10000
#define KNN     32
#define DG      256
#define ODIM    256
#define XSTRIDE 512   // 2*DG

// Scratch: fp16 transformed feature table + pre-split fp16 W (hi/lo)
__device__ __half g_hh[NN * XSTRIDE];
__device__ __half g_Whi[2 * ODIM * DG];
__device__ __half g_Wlo[2 * ODIM * DG];

__device__ __forceinline__ uint32_t smem_u32(const void* p) {
    uint32_t a;
    asm("{ .reg .u64 t; cvta.to.shared.u64 t, %1; cvt.u32.u64 %0, t; }"
        : "=r"(a) : "l"(p));
    return a;
}

// split a float pair into packed fp16 hi / lo pairs
__device__ __forceinline__ void cvt_pair_h(float f0, float f1,
                                           uint32_t& hi, uint32_t& lo) {
    __half2 hp = __floats2half2_rn(f0, f1);
    float2 hf = __half22float2(hp);
    __half2 lp = __floats2half2_rn(f0 - hf.x, f1 - hf.y);
    hi = *(uint32_t*)&hp;
    lo = *(uint32_t*)&lp;
}

__device__ __forceinline__ void ldm_x4(uint32_t* r, uint32_t addr) {
    asm volatile("ldmatrix.sync.aligned.m8n8.x4.shared.b16 {%0,%1,%2,%3}, [%4];"
                 : "=r"(r[0]), "=r"(r[1]), "=r"(r[2]), "=r"(r[3]) : "r"(addr));
}

__device__ __forceinline__ void mma_fp16(float* d, const uint32_t* a,
                                         const uint32_t* b) {
    asm volatile(
        "mma.sync.aligned.m16n8k16.row.col.f32.f16.f16.f32 "
        "{%0,%1,%2,%3}, {%4,%5,%6,%7}, {%8,%9}, {%0,%1,%2,%3};"
        : "+f"(d[0]), "+f"(d[1]), "+f"(d[2]), "+f"(d[3])
        : "r"(a[0]), "r"(a[1]), "r"(a[2]), "r"(a[3]), "r"(b[0]), "r"(b[1]));
}

// unpack 8 halves (uint4) into 8 floats
__device__ __forceinline__ void h8_to_f8(uint4 u, float* f) {
    float2 p;
    p = __half22float2(*(__half2*)&u.x); f[0] = p.x; f[1] = p.y;
    p = __half22float2(*(__half2*)&u.y); f[2] = p.x; f[3] = p.y;
    p = __half22float2(*(__half2*)&u.z); f[4] = p.x; f[5] = p.y;
    p = __half22float2(*(__half2*)&u.w); f[6] = p.x; f[7] = p.y;
}

// ---------------------------------------------------------------------------
// Kernel 0: pre-split W1/W2 into fp16 hi/lo.
// ---------------------------------------------------------------------------
__global__ __launch_bounds__(256)
void wcvt_kernel(const float* __restrict__ W1, const float* __restrict__ W2) {
    int idx = blockIdx.x * 256 + threadIdx.x;
    int wlin = idx * 4;
    int g = wlin >= ODIM * DG;
    int off = wlin - g * ODIM * DG;
    const float* __restrict__ W = g ? W2 : W1;
    float4 v = *(const float4*)&W[off];
    uint32_t h0, l0, h1, l1;
    cvt_pair_h(v.x, v.y, h0, l0);
    cvt_pair_h(v.z, v.w, h1, l1);
    *(uint2*)&g_Whi[wlin] = make_uint2(h0, h1);
    *(uint2*)&g_Wlo[wlin] = make_uint2(l0, l1);
}

// ---------------------------------------------------------------------------
// GEMM via HMMA fp16, 2 products: D = hA*hB + hA*lB  (A plain fp16).
// Block tile 64x256, 8 warps (2m x 4n). Grid (157, 2). Epilogue -> fp16 table.
// ---------------------------------------------------------------------------
#define STR 40   // fp16 per smem row (32 k + 8 pad): 80B stride, conflict-free

#define DSM_A     0
#define DSM_B_HI  (64 * STR * 2)                 // 5120
#define DSM_B_LO  (DSM_B_HI + 256 * STR * 2)     // 25600
#define DSM_FW    (DSM_B_LO + 256 * STR * 2)     // 46080
#define DSM_RED   (DSM_FW + 1024)
#define DSM_TOTAL (DSM_RED + 1024)               // 48128

__global__ __launch_bounds__(256)
void gemm_mma_kernel(const float* __restrict__ x,
                     const float* __restrict__ a1, const float* __restrict__ a2) {
    extern __shared__ char dsm[];
    __half* sA   = (__half*)(dsm + DSM_A);
    __half* sBhi = (__half*)(dsm + DSM_B_HI);
    __half* sBlo = (__half*)(dsm + DSM_B_LO);
    float* sFW = (float*)(dsm + DSM_FW);
    float* red = (float*)(dsm + DSM_RED);

    const int t    = threadIdx.x;
    const int lane = t & 31;
    const int wid  = t >> 5;
    const int wm   = wid >> 2;     // 0..1
    const int wn   = wid & 3;      // 0..3
    const int g    = blockIdx.y;
    const int i0   = blockIdx.x * 64;
    const float* __restrict__ a = g ? a2 : a1;
    const __half* __restrict__ Whi = g_Whi + g * ODIM * DG;
    const __half* __restrict__ Wlo = g_Wlo + g * ODIM * DG;

    // ---- fused fw = softmax(a) ----
    float av = a[t];
    red[t] = av; __syncthreads();
    #pragma unroll
    for (int s = 128; s > 0; s >>= 1) {
        if (t < s) red[t] = fmaxf(red[t], red[t + s]);
        __syncthreads();
    }
    float amax = red[0]; __syncthreads();
    float e = expf(av - amax);
    red[t] = e; __syncthreads();
    #pragma unroll
    for (int s = 128; s > 0; s >>= 1) {
        if (t < s) red[t] += red[t + s];
        __syncthreads();
    }
    float esum = red[0]; __syncthreads();
    sFW[t] = e / esum;

    const uint32_t sA0 = smem_u32(sA);
    const uint32_t sB0 = smem_u32(sBhi);
    const uint32_t sB1 = smem_u32(sBlo);
    const uint32_t aoff = (uint32_t)(((wm * 32 + (lane & 15)) * STR +
                                      ((lane >> 4) & 1) * 8) * 2);
    const uint32_t boff = (uint32_t)(((wn * 64 + (lane & 7) + ((lane >> 4) & 1) * 8) * STR +
                                      ((lane >> 3) & 1) * 8) * 2);

    float acc[2][8][4];
    #pragma unroll
    for (int mt = 0; mt < 2; ++mt)
        #pragma unroll
        for (int nt = 0; nt < 8; ++nt)
            #pragma unroll
            for (int q = 0; q < 4; ++q) acc[mt][nt][q] = 0.f;

    // A-fill coords: thread -> (row 0..63, kseg 0/8/16/24)
    const int arow = t >> 2;
    const int akk  = (t & 3) * 8;
    const bool arow_ok = (i0 + arow) < NN;
    const float* __restrict__ xrow =
        x + (size_t)(i0 + arow) * XSTRIDE + g * DG + akk;

    for (int c = 0; c < 8; ++c) {
        const int k0 = c * 32;
        // ---- A: load fp32 x, convert to plain fp16, store ----
        {
            float4 v0 = make_float4(0.f, 0.f, 0.f, 0.f);
            float4 v1 = make_float4(0.f, 0.f, 0.f, 0.f);
            if (arow_ok) {
                v0 = *(const float4*)(xrow + k0);
                v1 = *(const float4*)(xrow + k0 + 4);
            }
            __half2 p0 = __floats2half2_rn(v0.x, v0.y);
            __half2 p1 = __floats2half2_rn(v0.z, v0.w);
            __half2 p2 = __floats2half2_rn(v1.x, v1.y);
            __half2 p3 = __floats2half2_rn(v1.z, v1.w);
            *(uint4*)&sA[arow * STR + akk] =
                make_uint4(*(uint32_t*)&p0, *(uint32_t*)&p1,
                           *(uint32_t*)&p2, *(uint32_t*)&p3);
        }
        // ---- B: pre-split fp16 copy (4 segments of 8k per thread) ----
        #pragma unroll
        for (int q = 0; q < 4; ++q) {
            int lin = q * 256 + t;
            int row = lin >> 2;
            int kk  = (lin & 3) * 8;
            size_t widx = (size_t)row * DG + k0 + kk;
            *(uint4*)&sBhi[row * STR + kk] = *(const uint4*)&Whi[widx];
            *(uint4*)&sBlo[row * STR + kk] = *(const uint4*)&Wlo[widx];
        }
        __syncthreads();

        #pragma unroll
        for (int ks = 0; ks < 2; ++ks) {
            uint32_t ah[2][4];
            ldm_x4(ah[0], sA0 + aoff + ks * 32);
            ldm_x4(ah[1], sA0 + aoff + 16 * STR * 2 + ks * 32);
            #pragma unroll
            for (int nt2 = 0; nt2 < 4; ++nt2) {
                uint32_t bh[4], bl[4];
                ldm_x4(bh, sB0 + boff + nt2 * 16 * STR * 2 + ks * 32);
                ldm_x4(bl, sB1 + boff + nt2 * 16 * STR * 2 + ks * 32);
                #pragma unroll
                for (int mt = 0; mt < 2; ++mt) {
                    mma_fp16(acc[mt][nt2 * 2],     ah[mt], bh);
                    mma_fp16(acc[mt][nt2 * 2],     ah[mt], bl);
                    mma_fp16(acc[mt][nt2 * 2 + 1], ah[mt], bh + 2);
                    mma_fp16(acc[mt][nt2 * 2 + 1], ah[mt], bl + 2);
                }
            }
        }
        __syncthreads();
    }

    // ---- epilogue: scale by fw, clip, convert fp16, store ----
    #pragma unroll
    for (int mt = 0; mt < 2; ++mt) {
        int ra = i0 + wm * 32 + mt * 16 + (lane >> 2);
        int rb = ra + 8;
        #pragma unroll
        for (int nt = 0; nt < 8; ++nt) {
            int colg = wn * 64 + nt * 8 + (lane & 3) * 2;
            float f0 = sFW[colg], f1 = sFW[colg + 1];
            if (ra < NN) {
                float vx = fminf(1.f, fmaxf(-1.f, acc[mt][nt][0] * f0));
                float vy = fminf(1.f, fmaxf(-1.f, acc[mt][nt][1] * f1));
                *(__half2*)&g_hh[(size_t)ra * XSTRIDE + g * DG + colg] =
                    __floats2half2_rn(vx, vy);
            }
            if (rb < NN) {
                float vx = fminf(1.f, fmaxf(-1.f, acc[mt][nt][2] * f0));
                float vy = fminf(1.f, fmaxf(-1.f, acc[mt][nt][3] * f1));
                *(__half2*)&g_hh[(size_t)rb * XSTRIDE + g * DG + colg] =
                    __floats2half2_rn(vx, vy);
            }
        }
    }
}

// ---------------------------------------------------------------------------
// Attention v4 (fp16 table, proven): one block per (node, group), 256 threads.
// Warp w owns neighbors {w, w+8, w+16, w+24}; one warp spans a full 512B row.
// ---------------------------------------------------------------------------
__global__ __launch_bounds__(256)
void attn_kernel(const int* __restrict__ graph, float* __restrict__ out) {
    const int i = blockIdx.x;
    const int g = blockIdx.y;

    __shared__ int   idxs[KNN];
    __shared__ float score[KNN];
    __shared__ float agg[8][DG];

    const int t    = threadIdx.x;
    const int lane = t & 31;
    const int w    = t >> 5;

    if (t < KNN) idxs[t] = __ldg(&graph[(size_t)i * KNN + t]);
    __syncthreads();

    const __half* __restrict__ base = g_hh + g * DG + lane * 8;

    uint4 ovu = *(const uint4*)(base + (size_t)i * XSTRIDE);
    float ovf[8];
    h8_to_f8(ovu, ovf);

    uint4 nbu[4];
    #pragma unroll
    for (int r = 0; r < 4; ++r)
        nbu[r] = __ldcg((const uint4*)(base + (size_t)idxs[w + 8 * r] * XSTRIDE));
    float nbf[4][8];
    #pragma unroll
    for (int r = 0; r < 4; ++r) h8_to_f8(nbu[r], nbf[r]);

    #pragma unroll
    for (int r = 0; r < 4; ++r) {
        float s = 0.f;
        #pragma unroll
        for (int d = 0; d < 8; ++d) {
            float diff = ovf[d] - nbf[r][d];
            s = fmaf(diff, diff, s);
        }
        #pragma unroll
        for (int off = 16; off; off >>= 1) s += __shfl_xor_sync(0xffffffffu, s, off);
        if (lane == 0) score[w + 8 * r] = -s;
    }
    __syncthreads();

    if (t < KNN) {
        float s = score[t];
        float m = s;
        #pragma unroll
        for (int off = 16; off; off >>= 1) m = fmaxf(m, __shfl_xor_sync(0xffffffffu, m, off));
        float e = __expf(s - m);
        float sum = e;
        #pragma unroll
        for (int off = 16; off; off >>= 1) sum += __shfl_xor_sync(0xffffffffu, sum, off);
        score[t] = e / sum;
    }
    __syncthreads();

    float acc[8];
    #pragma unroll
    for (int d = 0; d < 8; ++d) acc[d] = 0.f;
    #pragma unroll
    for (int r = 0; r < 4; ++r) {
        float wt = score[w + 8 * r];
        #pragma unroll
        for (int d = 0; d < 8; ++d)
            acc[d] = fmaf(wt, nbf[r][d], acc[d]);
    }
    *(float4*)&agg[w][lane * 8]     = make_float4(acc[0], acc[1], acc[2], acc[3]);
    *(float4*)&agg[w][lane * 8 + 4] = make_float4(acc[4], acc[5], acc[6], acc[7]);
    __syncthreads();

    float s = 0.f;
    #pragma unroll
    for (int w8 = 0; w8 < 8; ++w8) s += agg[w8][t];
    out[(size_t)i * XSTRIDE + g * DG + t] = s;
}

// ---------------------------------------------------------------------------
// Launch
// ---------------------------------------------------------------------------
extern "C" void kernel_launch(void* const* d_in, const int* in_sizes, int n_in,
                              void* d_out, int out_size) {
    const float* x     = (const float*)d_in[0];
    const float* W1    = (const float*)d_in[1];
    const float* a1    = (const float*)d_in[2];
    const float* W2    = (const float*)d_in[3];
    const float* a2    = (const float*)d_in[4];
    const int*   graph = (const int*)d_in[5];
    float* out = (float*)d_out;

    static int smem_set = 0;
    if (!smem_set) {
        cudaFuncSetAttribute(gemm_mma_kernel,
                             cudaFuncAttributeMaxDynamicSharedMemorySize, DSM_TOTAL);
        smem_set = 1;
    }

    wcvt_kernel<<<2 * ODIM * DG / (256 * 4), 256>>>(W1, W2);

    dim3 ggrid((NN + 63) / 64, 2);
    gemm_mma_kernel<<<ggrid, 256, DSM_TOTAL>>>(x, a1, a2);

    dim3 agrid(NN, 2);
    attn_kernel<<<agrid, 256>>>(graph, out);
}

// round 12
// speedup vs baseline: 1.6447x; 1.1246x over previous
#include <cuda_runtime.h>
#include <cuda_bf16.h>
#include <cuda_fp16.h>
#include <cstdint>

// Problem constants (fixed by the reference)
#define NN      10000
#define KNN     32
#define DG      256
#define ODIM    256
#define XSTRIDE 512   // 2*DG

// Scratch: fp16 transformed feature table + fp16 W
__device__ __half g_hh[NN * XSTRIDE];
__device__ __half g_Wh[2 * ODIM * DG];

__device__ __forceinline__ uint32_t smem_u32(const void* p) {
    uint32_t a;
    asm("{ .reg .u64 t; cvta.to.shared.u64 t, %1; cvt.u32.u64 %0, t; }"
        : "=r"(a) : "l"(p));
    return a;
}

__device__ __forceinline__ void ldm_x4(uint32_t* r, uint32_t addr) {
    asm volatile("ldmatrix.sync.aligned.m8n8.x4.shared.b16 {%0,%1,%2,%3}, [%4];"
                 : "=r"(r[0]), "=r"(r[1]), "=r"(r[2]), "=r"(r[3]) : "r"(addr));
}

__device__ __forceinline__ void mma_fp16(float* d, const uint32_t* a,
                                         const uint32_t* b) {
    asm volatile(
        "mma.sync.aligned.m16n8k16.row.col.f32.f16.f16.f32 "
        "{%0,%1,%2,%3}, {%4,%5,%6,%7}, {%8,%9}, {%0,%1,%2,%3};"
        : "+f"(d[0]), "+f"(d[1]), "+f"(d[2]), "+f"(d[3])
        : "r"(a[0]), "r"(a[1]), "r"(a[2]), "r"(a[3]), "r"(b[0]), "r"(b[1]));
}

// unpack 8 halves (uint4) into 8 floats
__device__ __forceinline__ void h8_to_f8(uint4 u, float* f) {
    float2 p;
    p = __half22float2(*(__half2*)&u.x); f[0] = p.x; f[1] = p.y;
    p = __half22float2(*(__half2*)&u.y); f[2] = p.x; f[3] = p.y;
    p = __half22float2(*(__half2*)&u.z); f[4] = p.x; f[5] = p.y;
    p = __half22float2(*(__half2*)&u.w); f[6] = p.x; f[7] = p.y;
}

// ---------------------------------------------------------------------------
// Kernel 0: convert W1/W2 to fp16.
// ---------------------------------------------------------------------------
__global__ __launch_bounds__(256)
void wcvt_kernel(const float* __restrict__ W1, const float* __restrict__ W2) {
    int idx = blockIdx.x * 256 + threadIdx.x;
    int wlin = idx * 4;
    int g = wlin >= ODIM * DG;
    int off = wlin - g * ODIM * DG;
    const float* __restrict__ W = g ? W2 : W1;
    float4 v = *(const float4*)&W[off];
    __half2 p0 = __floats2half2_rn(v.x, v.y);
    __half2 p1 = __floats2half2_rn(v.z, v.w);
    *(uint2*)&g_Wh[wlin] = make_uint2(*(uint32_t*)&p0, *(uint32_t*)&p1);
}

// ---------------------------------------------------------------------------
// GEMM via HMMA plain fp16, fp32 accumulate:
// Block tile 64x256, 8 warps (2m x 4n). Grid (157, 2). Epilogue -> fp16 table.
// ---------------------------------------------------------------------------
#define STR 40   // fp16 per smem row (32 k + 8 pad): 80B stride, conflict-free

#define DSM_A     0
#define DSM_B     (64 * STR * 2)                 // 5120
#define DSM_FW    (DSM_B + 256 * STR * 2)        // 25600
#define DSM_RED   (DSM_FW + 1024)                // 26624
#define DSM_TOTAL (DSM_RED + 1024)               // 27648

__global__ __launch_bounds__(256)
void gemm_mma_kernel(const float* __restrict__ x,
                     const float* __restrict__ a1, const float* __restrict__ a2) {
    extern __shared__ char dsm[];
    __half* sA = (__half*)(dsm + DSM_A);
    __half* sB = (__half*)(dsm + DSM_B);
    float* sFW = (float*)(dsm + DSM_FW);
    float* red = (float*)(dsm + DSM_RED);

    const int t    = threadIdx.x;
    const int lane = t & 31;
    const int wid  = t >> 5;
    const int wm   = wid >> 2;     // 0..1
    const int wn   = wid & 3;      // 0..3
    const int g    = blockIdx.y;
    const int i0   = blockIdx.x * 64;
    const float* __restrict__ a = g ? a2 : a1;
    const __half* __restrict__ Wh = g_Wh + g * ODIM * DG;

    // ---- fused fw = softmax(a) ----
    float av = a[t];
    red[t] = av; __syncthreads();
    #pragma unroll
    for (int s = 128; s > 0; s >>= 1) {
        if (t < s) red[t] = fmaxf(red[t], red[t + s]);
        __syncthreads();
    }
    float amax = red[0]; __syncthreads();
    float e = expf(av - amax);
    red[t] = e; __syncthreads();
    #pragma unroll
    for (int s = 128; s > 0; s >>= 1) {
        if (t < s) red[t] += red[t + s];
        __syncthreads();
    }
    float esum = red[0]; __syncthreads();
    sFW[t] = e / esum;

    const uint32_t sA0 = smem_u32(sA);
    const uint32_t sB0 = smem_u32(sB);
    const uint32_t aoff = (uint32_t)(((wm * 32 + (lane & 15)) * STR +
                                      ((lane >> 4) & 1) * 8) * 2);
    const uint32_t boff = (uint32_t)(((wn * 64 + (lane & 7) + ((lane >> 4) & 1) * 8) * STR +
                                      ((lane >> 3) & 1) * 8) * 2);

    float acc[2][8][4];
    #pragma unroll
    for (int mt = 0; mt < 2; ++mt)
        #pragma unroll
        for (int nt = 0; nt < 8; ++nt)
            #pragma unroll
            for (int q = 0; q < 4; ++q) acc[mt][nt][q] = 0.f;

    const int arow = t >> 2;
    const int akk  = (t & 3) * 8;
    const bool arow_ok = (i0 + arow) < NN;
    const float* __restrict__ xrow =
        x + (size_t)(i0 + arow) * XSTRIDE + g * DG + akk;

    for (int c = 0; c < 8; ++c) {
        const int k0 = c * 32;
        // ---- A: load fp32 x, convert fp16, store ----
        {
            float4 v0 = make_float4(0.f, 0.f, 0.f, 0.f);
            float4 v1 = make_float4(0.f, 0.f, 0.f, 0.f);
            if (arow_ok) {
                v0 = *(const float4*)(xrow + k0);
                v1 = *(const float4*)(xrow + k0 + 4);
            }
            __half2 p0 = __floats2half2_rn(v0.x, v0.y);
            __half2 p1 = __floats2half2_rn(v0.z, v0.w);
            __half2 p2 = __floats2half2_rn(v1.x, v1.y);
            __half2 p3 = __floats2half2_rn(v1.z, v1.w);
            *(uint4*)&sA[arow * STR + akk] =
                make_uint4(*(uint32_t*)&p0, *(uint32_t*)&p1,
                           *(uint32_t*)&p2, *(uint32_t*)&p3);
        }
        // ---- B: fp16 copy (4 segments of 8k per thread) ----
        #pragma unroll
        for (int q = 0; q < 4; ++q) {
            int lin = q * 256 + t;
            int row = lin >> 2;
            int kk  = (lin & 3) * 8;
            *(uint4*)&sB[row * STR + kk] =
                *(const uint4*)&Wh[(size_t)row * DG + k0 + kk];
        }
        __syncthreads();

        #pragma unroll
        for (int ks = 0; ks < 2; ++ks) {
            uint32_t ah[2][4];
            ldm_x4(ah[0], sA0 + aoff + ks * 32);
            ldm_x4(ah[1], sA0 + aoff + 16 * STR * 2 + ks * 32);
            #pragma unroll
            for (int nt2 = 0; nt2 < 4; ++nt2) {
                uint32_t bh[4];
                ldm_x4(bh, sB0 + boff + nt2 * 16 * STR * 2 + ks * 32);
                #pragma unroll
                for (int mt = 0; mt < 2; ++mt) {
                    mma_fp16(acc[mt][nt2 * 2],     ah[mt], bh);
                    mma_fp16(acc[mt][nt2 * 2 + 1], ah[mt], bh + 2);
                }
            }
        }
        __syncthreads();
    }

    // ---- epilogue: scale by fw, clip, convert fp16, store ----
    #pragma unroll
    for (int mt = 0; mt < 2; ++mt) {
        int ra = i0 + wm * 32 + mt * 16 + (lane >> 2);
        int rb = ra + 8;
        #pragma unroll
        for (int nt = 0; nt < 8; ++nt) {
            int colg = wn * 64 + nt * 8 + (lane & 3) * 2;
            float f0 = sFW[colg], f1 = sFW[colg + 1];
            if (ra < NN) {
                float vx = fminf(1.f, fmaxf(-1.f, acc[mt][nt][0] * f0));
                float vy = fminf(1.f, fmaxf(-1.f, acc[mt][nt][1] * f1));
                *(__half2*)&g_hh[(size_t)ra * XSTRIDE + g * DG + colg] =
                    __floats2half2_rn(vx, vy);
            }
            if (rb < NN) {
                float vx = fminf(1.f, fmaxf(-1.f, acc[mt][nt][2] * f0));
                float vy = fminf(1.f, fmaxf(-1.f, acc[mt][nt][3] * f1));
                *(__half2*)&g_hh[(size_t)rb * XSTRIDE + g * DG + colg] =
                    __floats2half2_rn(vx, vy);
            }
        }
    }
}

// ---------------------------------------------------------------------------
// Attention v5: 2 nodes per block (grid 5000 x 2), 256 threads.
// Warp w serves node (w>>2); each warp gathers 8 neighbor rows (MLP=8),
// held as raw fp16 uint4 (low regs), converted on use.
// ---------------------------------------------------------------------------
__global__ __launch_bounds__(256)
void attn_kernel(const int* __restrict__ graph, float* __restrict__ out) {
    const int i0 = blockIdx.x * 2;
    const int g  = blockIdx.y;

    __shared__ int   idxs[2 * KNN];
    __shared__ float score[2 * KNN];
    __shared__ float agg[8][DG];    // rows 0-3: node 0, rows 4-7: node 1

    const int t    = threadIdx.x;
    const int lane = t & 31;
    const int w    = t >> 5;
    const int n    = w >> 2;        // node within pair
    const int wl   = w & 3;         // warp within node

    if (t < 2 * KNN) idxs[t] = __ldg(&graph[(size_t)i0 * KNN + t]);
    __syncthreads();

    const __half* __restrict__ base = g_hh + g * DG + lane * 8;

    // self row for this warp's node
    uint4 ovu = *(const uint4*)(base + (size_t)(i0 + n) * XSTRIDE);
    float ovf[8];
    h8_to_f8(ovu, ovf);

    // gather 8 neighbor rows (512B contiguous each, MLP=8)
    uint4 nbu[8];
    #pragma unroll
    for (int r = 0; r < 8; ++r)
        nbu[r] = __ldcg((const uint4*)(base +
                    (size_t)idxs[n * KNN + wl + 4 * r] * XSTRIDE));

    // scores
    #pragma unroll
    for (int r = 0; r < 8; ++r) {
        float f[8];
        h8_to_f8(nbu[r], f);
        float s = 0.f;
        #pragma unroll
        for (int d = 0; d < 8; ++d) {
            float diff = ovf[d] - f[d];
            s = fmaf(diff, diff, s);
        }
        #pragma unroll
        for (int off = 16; off; off >>= 1) s += __shfl_xor_sync(0xffffffffu, s, off);
        if (lane == 0) score[n * KNN + wl + 4 * r] = -s;
    }
    __syncthreads();

    // softmax: warp 0 -> node 0, warp 1 -> node 1
    if (t < 2 * KNN) {
        float s = score[t];
        float m = s;
        #pragma unroll
        for (int off = 16; off; off >>= 1) m = fmaxf(m, __shfl_xor_sync(0xffffffffu, m, off));
        float e = __expf(s - m);
        float sum = e;
        #pragma unroll
        for (int off = 16; off; off >>= 1) sum += __shfl_xor_sync(0xffffffffu, sum, off);
        score[t] = e / sum;
    }
    __syncthreads();

    // weighted partial aggregate (8 neighbors per warp)
    float acc[8];
    #pragma unroll
    for (int d = 0; d < 8; ++d) acc[d] = 0.f;
    #pragma unroll
    for (int r = 0; r < 8; ++r) {
        float f[8];
        h8_to_f8(nbu[r], f);
        float wt = score[n * KNN + wl + 4 * r];
        #pragma unroll
        for (int d = 0; d < 8; ++d)
            acc[d] = fmaf(wt, f[d], acc[d]);
    }
    *(float4*)&agg[w][lane * 8]     = make_float4(acc[0], acc[1], acc[2], acc[3]);
    *(float4*)&agg[w][lane * 8 + 4] = make_float4(acc[4], acc[5], acc[6], acc[7]);
    __syncthreads();

    // cross-warp column sums + store (thread t = column t, both nodes)
    float s0 = (agg[0][t] + agg[1][t]) + (agg[2][t] + agg[3][t]);
    float s1 = (agg[4][t] + agg[5][t]) + (agg[6][t] + agg[7][t]);
    out[(size_t)i0 * XSTRIDE + g * DG + t] = s0;
    out[(size_t)(i0 + 1) * XSTRIDE + g * DG + t] = s1;
}

// ---------------------------------------------------------------------------
// Launch
// ---------------------------------------------------------------------------
extern "C" void kernel_launch(void* const* d_in, const int* in_sizes, int n_in,
                              void* d_out, int out_size) {
    const float* x     = (const float*)d_in[0];
    const float* W1    = (const float*)d_in[1];
    const float* a1    = (const float*)d_in[2];
    const float* W2    = (const float*)d_in[3];
    const float* a2    = (const float*)d_in[4];
    const int*   graph = (const int*)d_in[5];
    float* out = (float*)d_out;

    static int smem_set = 0;
    if (!smem_set) {
        cudaFuncSetAttribute(gemm_mma_kernel,
                             cudaFuncAttributeMaxDynamicSharedMemorySize, DSM_TOTAL);
        smem_set = 1;
    }

    wcvt_kernel<<<2 * ODIM * DG / (256 * 4), 256>>>(W1, W2);

    dim3 ggrid((NN + 63) / 64, 2);
    gemm_mma_kernel<<<ggrid, 256, DSM_TOTAL>>>(x, a1, a2);

    dim3 agrid(NN / 2, 2);
    attn_kernel<<<agrid, 256>>>(graph, out);
}

// round 13
// speedup vs baseline: 2.0506x; 1.2468x over previous
#include <cuda_runtime.h>
#include <cuda_bf16.h>
#include <cuda_fp16.h>
#include <cstdint>

// Problem constants (fixed by the reference)
#define NN      10000
#define KNN     32
#define DG      256
#define ODIM    256
#define XSTRIDE 512   // 2*DG

// Scratch: fp16 transformed feature table + fp16 W
__device__ __half g_hh[NN * XSTRIDE];
__device__ __half g_Wh[2 * ODIM * DG];

__device__ __forceinline__ uint32_t smem_u32(const void* p) {
    uint32_t a;
    asm("{ .reg .u64 t; cvta.to.shared.u64 t, %1; cvt.u32.u64 %0, t; }"
        : "=r"(a) : "l"(p));
    return a;
}

__device__ __forceinline__ void ldm_x4(uint32_t* r, uint32_t addr) {
    asm volatile("ldmatrix.sync.aligned.m8n8.x4.shared.b16 {%0,%1,%2,%3}, [%4];"
                 : "=r"(r[0]), "=r"(r[1]), "=r"(r[2]), "=r"(r[3]) : "r"(addr));
}

__device__ __forceinline__ void mma_fp16(float* d, const uint32_t* a,
                                         const uint32_t* b) {
    asm volatile(
        "mma.sync.aligned.m16n8k16.row.col.f32.f16.f16.f32 "
        "{%0,%1,%2,%3}, {%4,%5,%6,%7}, {%8,%9}, {%0,%1,%2,%3};"
        : "+f"(d[0]), "+f"(d[1]), "+f"(d[2]), "+f"(d[3])
        : "r"(a[0]), "r"(a[1]), "r"(a[2]), "r"(a[3]), "r"(b[0]), "r"(b[1]));
}

__device__ __forceinline__ void cp_async16(uint32_t smem, const void* gptr) {
    asm volatile("cp.async.cg.shared.global [%0], [%1], 16;"
                 :: "r"(smem), "l"(gptr) : "memory");
}
__device__ __forceinline__ void cp_commit() {
    asm volatile("cp.async.commit_group;" ::: "memory");
}
__device__ __forceinline__ void cp_wait0() {
    asm volatile("cp.async.wait_group 0;" ::: "memory");
}

// unpack 8 halves (uint4) into 8 floats
__device__ __forceinline__ void h8_to_f8(uint4 u, float* f) {
    float2 p;
    p = __half22float2(*(__half2*)&u.x); f[0] = p.x; f[1] = p.y;
    p = __half22float2(*(__half2*)&u.y); f[2] = p.x; f[3] = p.y;
    p = __half22float2(*(__half2*)&u.z); f[4] = p.x; f[5] = p.y;
    p = __half22float2(*(__half2*)&u.w); f[6] = p.x; f[7] = p.y;
}

// ---------------------------------------------------------------------------
// Kernel 0: convert W1/W2 to fp16.
// ---------------------------------------------------------------------------
__global__ __launch_bounds__(256)
void wcvt_kernel(const float* __restrict__ W1, const float* __restrict__ W2) {
    int idx = blockIdx.x * 256 + threadIdx.x;
    int wlin = idx * 4;
    int g = wlin >= ODIM * DG;
    int off = wlin - g * ODIM * DG;
    const float* __restrict__ W = g ? W2 : W1;
    float4 v = *(const float4*)&W[off];
    __half2 p0 = __floats2half2_rn(v.x, v.y);
    __half2 p1 = __floats2half2_rn(v.z, v.w);
    *(uint2*)&g_Wh[wlin] = make_uint2(*(uint32_t*)&p0, *(uint32_t*)&p1);
}

// ---------------------------------------------------------------------------
// GEMM via HMMA fp16, fp32 accumulate, SOFTWARE-PIPELINED fills:
//  - B staged via cp.async (double-buffered smem)
//  - A prefetched to regs at loop top, cvt+STS after MMA section
// Block tile 64x256, 8 warps (2m x 4n). Grid (157, 2). Epilogue -> fp16 table.
// ---------------------------------------------------------------------------
#define STR 40   // fp16 per smem row (32 k + 8 pad): 80B stride, conflict-free

#define ABUF      (64 * STR * 2)                 // 5120
#define BBUF      (256 * STR * 2)                // 20480
#define DSM_A     0                               // 2 x ABUF
#define DSM_B     (2 * ABUF)                      // 10240, 2 x BBUF
#define DSM_FW    (DSM_B + 2 * BBUF)              // 51200
#define DSM_RED   (DSM_FW + 1024)                 // 52224
#define DSM_TOTAL (DSM_RED + 1024)                // 53248

__global__ __launch_bounds__(256)
void gemm_mma_kernel(const float* __restrict__ x,
                     const float* __restrict__ a1, const float* __restrict__ a2) {
    extern __shared__ char dsm[];
    __half* sA = (__half*)(dsm + DSM_A);
    __half* sB = (__half*)(dsm + DSM_B);
    float* sFW = (float*)(dsm + DSM_FW);
    float* red = (float*)(dsm + DSM_RED);

    const int t    = threadIdx.x;
    const int lane = t & 31;
    const int wid  = t >> 5;
    const int wm   = wid >> 2;     // 0..1
    const int wn   = wid & 3;      // 0..3
    const int g    = blockIdx.y;
    const int i0   = blockIdx.x * 64;
    const float* __restrict__ a = g ? a2 : a1;
    const __half* __restrict__ Wh = g_Wh + g * ODIM * DG;

    // ---- fused fw = softmax(a) ----
    float av = a[t];
    red[t] = av; __syncthreads();
    #pragma unroll
    for (int s = 128; s > 0; s >>= 1) {
        if (t < s) red[t] = fmaxf(red[t], red[t + s]);
        __syncthreads();
    }
    float amax = red[0]; __syncthreads();
    float e = expf(av - amax);
    red[t] = e; __syncthreads();
    #pragma unroll
    for (int s = 128; s > 0; s >>= 1) {
        if (t < s) red[t] += red[t + s];
        __syncthreads();
    }
    float esum = red[0]; __syncthreads();
    sFW[t] = e / esum;

    const uint32_t sAb = smem_u32(sA);
    const uint32_t sBb = smem_u32(sB);
    const uint32_t aoff = (uint32_t)(((wm * 32 + (lane & 15)) * STR +
                                      ((lane >> 4) & 1) * 8) * 2);
    const uint32_t boff = (uint32_t)(((wn * 64 + (lane & 7) + ((lane >> 4) & 1) * 8) * STR +
                                      ((lane >> 3) & 1) * 8) * 2);

    float acc[2][8][4];
    #pragma unroll
    for (int mt = 0; mt < 2; ++mt)
        #pragma unroll
        for (int nt = 0; nt < 8; ++nt)
            #pragma unroll
            for (int q = 0; q < 4; ++q) acc[mt][nt][q] = 0.f;

    // fill coordinates
    const int arow = t >> 2;
    const int akk  = (t & 3) * 8;
    const bool arow_ok = (i0 + arow) < NN;
    const float* __restrict__ xrow =
        x + (size_t)(i0 + arow) * XSTRIDE + g * DG + akk;
    const uint32_t aSts = sAb + (uint32_t)((arow * STR + akk) * 2);

    // B fill: 4 segments per thread
    int brow[4], bkk[4];
    #pragma unroll
    for (int q = 0; q < 4; ++q) {
        int lin = q * 256 + t;
        brow[q] = lin >> 2;
        bkk[q]  = (lin & 3) * 8;
    }

    // ---- prologue: stage chunk 0 ----
    {
        #pragma unroll
        for (int q = 0; q < 4; ++q)
            cp_async16(sBb + (uint32_t)((brow[q] * STR + bkk[q]) * 2),
                       &Wh[(size_t)brow[q] * DG + bkk[q]]);
        cp_commit();
        float4 v0 = make_float4(0.f, 0.f, 0.f, 0.f);
        float4 v1 = make_float4(0.f, 0.f, 0.f, 0.f);
        if (arow_ok) {
            v0 = *(const float4*)(xrow);
            v1 = *(const float4*)(xrow + 4);
        }
        __half2 p0 = __floats2half2_rn(v0.x, v0.y);
        __half2 p1 = __floats2half2_rn(v0.z, v0.w);
        __half2 p2 = __floats2half2_rn(v1.x, v1.y);
        __half2 p3 = __floats2half2_rn(v1.z, v1.w);
        *(uint4*)(dsm + (aSts - sAb)) = make_uint4(
            *(uint32_t*)&p0, *(uint32_t*)&p1, *(uint32_t*)&p2, *(uint32_t*)&p3);
        cp_wait0();
    }
    __syncthreads();

    for (int c = 0; c < 8; ++c) {
        const int buf  = c & 1;
        const int nbuf = buf ^ 1;
        const bool pf = c < 7;
        float4 v0, v1;

        // ---- prefetch chunk c+1 (B via cp.async, A into regs) ----
        if (pf) {
            const int kn = (c + 1) * 32;
            #pragma unroll
            for (int q = 0; q < 4; ++q)
                cp_async16(sBb + (uint32_t)(nbuf * BBUF + (brow[q] * STR + bkk[q]) * 2),
                           &Wh[(size_t)brow[q] * DG + kn + bkk[q]]);
            cp_commit();
            if (arow_ok) {
                v0 = *(const float4*)(xrow + kn);
                v1 = *(const float4*)(xrow + kn + 4);
            } else {
                v0 = make_float4(0.f, 0.f, 0.f, 0.f);
                v1 = make_float4(0.f, 0.f, 0.f, 0.f);
            }
        }

        // ---- MMA on current buffers ----
        const uint32_t sA0 = sAb + buf * ABUF;
        const uint32_t sB0 = sBb + buf * BBUF;
        #pragma unroll
        for (int ks = 0; ks < 2; ++ks) {
            uint32_t ah[2][4];
            ldm_x4(ah[0], sA0 + aoff + ks * 32);
            ldm_x4(ah[1], sA0 + aoff + 16 * STR * 2 + ks * 32);
            #pragma unroll
            for (int nt2 = 0; nt2 < 4; ++nt2) {
                uint32_t bh[4];
                ldm_x4(bh, sB0 + boff + nt2 * 16 * STR * 2 + ks * 32);
                #pragma unroll
                for (int mt = 0; mt < 2; ++mt) {
                    mma_fp16(acc[mt][nt2 * 2],     ah[mt], bh);
                    mma_fp16(acc[mt][nt2 * 2 + 1], ah[mt], bh + 2);
                }
            }
        }

        // ---- store prefetched A into next buffer ----
        if (pf) {
            __half2 p0 = __floats2half2_rn(v0.x, v0.y);
            __half2 p1 = __floats2half2_rn(v0.z, v0.w);
            __half2 p2 = __floats2half2_rn(v1.x, v1.y);
            __half2 p3 = __floats2half2_rn(v1.z, v1.w);
            *(uint4*)(dsm + nbuf * ABUF + (aSts - sAb)) = make_uint4(
                *(uint32_t*)&p0, *(uint32_t*)&p1, *(uint32_t*)&p2, *(uint32_t*)&p3);
            cp_wait0();
        }
        __syncthreads();
    }

    // ---- epilogue: scale by fw, clip, convert fp16, store ----
    #pragma unroll
    for (int mt = 0; mt < 2; ++mt) {
        int ra = i0 + wm * 32 + mt * 16 + (lane >> 2);
        int rb = ra + 8;
        #pragma unroll
        for (int nt = 0; nt < 8; ++nt) {
            int colg = wn * 64 + nt * 8 + (lane & 3) * 2;
            float f0 = sFW[colg], f1 = sFW[colg + 1];
            if (ra < NN) {
                float vx = fminf(1.f, fmaxf(-1.f, acc[mt][nt][0] * f0));
                float vy = fminf(1.f, fmaxf(-1.f, acc[mt][nt][1] * f1));
                *(__half2*)&g_hh[(size_t)ra * XSTRIDE + g * DG + colg] =
                    __floats2half2_rn(vx, vy);
            }
            if (rb < NN) {
                float vx = fminf(1.f, fmaxf(-1.f, acc[mt][nt][2] * f0));
                float vy = fminf(1.f, fmaxf(-1.f, acc[mt][nt][3] * f1));
                *(__half2*)&g_hh[(size_t)rb * XSTRIDE + g * DG + colg] =
                    __floats2half2_rn(vx, vy);
            }
        }
    }
}

// ---------------------------------------------------------------------------
// Attention v6: 2 nodes per block (grid 5000 x 2), 256 threads.
// Warp w serves node (w>>2); 8 neighbor rows per warp (MLP=8, raw fp16).
// Scores computed in half2 (HSUB2/HFMA2) -> ~half the score-phase instrs.
// ---------------------------------------------------------------------------
__global__ __launch_bounds__(256)
void attn_kernel(const int* __restrict__ graph, float* __restrict__ out) {
    const int i0 = blockIdx.x * 2;
    const int g  = blockIdx.y;

    __shared__ int   idxs[2 * KNN];
    __shared__ float score[2 * KNN];
    __shared__ float agg[8][DG];    // rows 0-3: node 0, rows 4-7: node 1

    const int t    = threadIdx.x;
    const int lane = t & 31;
    const int w    = t >> 5;
    const int n    = w >> 2;        // node within pair
    const int wl   = w & 3;         // warp within node

    if (t < 2 * KNN) idxs[t] = __ldg(&graph[(size_t)i0 * KNN + t]);
    __syncthreads();

    const __half* __restrict__ base = g_hh + g * DG + lane * 8;

    // self row (raw fp16)
    uint4 ovu = *(const uint4*)(base + (size_t)(i0 + n) * XSTRIDE);
    const __half2* ov2 = (const __half2*)&ovu;

    // gather 8 neighbor rows (512B contiguous each, MLP=8)
    uint4 nbu[8];
    #pragma unroll
    for (int r = 0; r < 8; ++r)
        nbu[r] = __ldcg((const uint4*)(base +
                    (size_t)idxs[n * KNN + wl + 4 * r] * XSTRIDE));

    // scores in half2
    #pragma unroll
    for (int r = 0; r < 8; ++r) {
        const __half2* nb2 = (const __half2*)&nbu[r];
        __half2 acc2 = __float2half2_rn(0.f);
        #pragma unroll
        for (int d = 0; d < 4; ++d) {
            __half2 df = __hsub2(ov2[d], nb2[d]);
            acc2 = __hfma2(df, df, acc2);
        }
        float2 sf = __half22float2(acc2);
        float s = sf.x + sf.y;
        #pragma unroll
        for (int off = 16; off; off >>= 1) s += __shfl_xor_sync(0xffffffffu, s, off);
        if (lane == 0) score[n * KNN + wl + 4 * r] = -s;
    }
    __syncthreads();

    // softmax: warp 0 -> node 0, warp 1 -> node 1
    if (t < 2 * KNN) {
        float s = score[t];
        float m = s;
        #pragma unroll
        for (int off = 16; off; off >>= 1) m = fmaxf(m, __shfl_xor_sync(0xffffffffu, m, off));
        float e = __expf(s - m);
        float sum = e;
        #pragma unroll
        for (int off = 16; off; off >>= 1) sum += __shfl_xor_sync(0xffffffffu, sum, off);
        score[t] = e / sum;
    }
    __syncthreads();

    // weighted partial aggregate (fp32)
    float acc[8];
    #pragma unroll
    for (int d = 0; d < 8; ++d) acc[d] = 0.f;
    #pragma unroll
    for (int r = 0; r < 8; ++r) {
        float f[8];
        h8_to_f8(nbu[r], f);
        float wt = score[n * KNN + wl + 4 * r];
        #pragma unroll
        for (int d = 0; d < 8; ++d)
            acc[d] = fmaf(wt, f[d], acc[d]);
    }
    *(float4*)&agg[w][lane * 8]     = make_float4(acc[0], acc[1], acc[2], acc[3]);
    *(float4*)&agg[w][lane * 8 + 4] = make_float4(acc[4], acc[5], acc[6], acc[7]);
    __syncthreads();

    // cross-warp column sums + store (thread t = column t, both nodes)
    float s0 = (agg[0][t] + agg[1][t]) + (agg[2][t] + agg[3][t]);
    float s1 = (agg[4][t] + agg[5][t]) + (agg[6][t] + agg[7][t]);
    out[(size_t)i0 * XSTRIDE + g * DG + t] = s0;
    out[(size_t)(i0 + 1) * XSTRIDE + g * DG + t] = s1;
}

// ---------------------------------------------------------------------------
// Launch
// ---------------------------------------------------------------------------
extern "C" void kernel_launch(void* const* d_in, const int* in_sizes, int n_in,
                              void* d_out, int out_size) {
    const float* x     = (const float*)d_in[0];
    const float* W1    = (const float*)d_in[1];
    const float* a1    = (const float*)d_in[2];
    const float* W2    = (const float*)d_in[3];
    const float* a2    = (const float*)d_in[4];
    const int*   graph = (const int*)d_in[5];
    float* out = (float*)d_out;

    static int smem_set = 0;
    if (!smem_set) {
        cudaFuncSetAttribute(gemm_mma_kernel,
                             cudaFuncAttributeMaxDynamicSharedMemorySize, DSM_TOTAL);
        smem_set = 1;
    }

    wcvt_kernel<<<2 * ODIM * DG / (256 * 4), 256>>>(W1, W2);

    dim3 ggrid((NN + 63) / 64, 2);
    gemm_mma_kernel<<<ggrid, 256, DSM_TOTAL>>>(x, a1, a2);

    dim3 agrid(NN / 2, 2);
    attn_kernel<<<agrid, 256>>>(graph, out);
}